// round 12
// baseline (speedup 1.0000x reference)
#include <cuda_runtime.h>
#include <cuda_bf16.h>
#include <cuda_fp8.h>
#include <stdint.h>

#define SEQ 4096
#define E   2048
#define SE  (SEQ * E)      // 8M
#define EE  (E * E)        // 4M
#define SS  ((size_t)SEQ * SEQ)

// Per-tensor fp8 hi-scales (power of 2): x:32, W:1024, q/k/vT:64, w:256.
// lo-scale = 512 * hi-scale (global ratio) so both fp8 cross terms share one
// accumulator. Correction divisors per GEMM (exact powers of two):
//   qkv: 32*1024*512 = 2^24,  s: 64*64*512 = 2^21,  out: 256*64*512 = 2^23
#define INV_QKV (1.0f / 16777216.0f)
#define INV_S   (1.0f / 2097152.0f)
#define INV_OUT (1.0f / 8388608.0f)

// ---------------------------------------------------------------------------
// Scratch (__device__ globals per allocation-free rule)
// ---------------------------------------------------------------------------
__device__ __nv_bfloat16 g_xh[SE], g_Wqh[EE], g_Wkh[EE], g_Wvh[EE];
__device__ __nv_bfloat16 g_qh[SE], g_kh[SE], g_vTh[SE], g_wh[SS];
__device__ uint8_t g_x8h[SE],  g_x8l[SE];
__device__ uint8_t g_Wq8h[EE], g_Wq8l[EE], g_Wk8h[EE], g_Wk8l[EE], g_Wv8h[EE], g_Wv8l[EE];
__device__ uint8_t g_q8h[SE],  g_q8l[SE],  g_k8h[SE],  g_k8l[SE],  g_vT8h[SE], g_vT8l[SE];
__device__ uint8_t g_w8h[SS],  g_w8l[SS];
__device__ float g_p1[3 * SE], g_p2[3 * SE];   // fp32 partials (main / corr)
__device__ float g_s[SS], g_s2[SS];            // s-GEMM partials

// ---------------------------------------------------------------------------
// PTX helpers
// ---------------------------------------------------------------------------
__device__ __forceinline__ uint32_t smem_u32(const void* p) {
    uint32_t a;
    asm("{ .reg .u64 t; cvta.to.shared.u64 t, %1; cvt.u32.u64 %0, t; }" : "=r"(a) : "l"(p));
    return a;
}
#define CP_ASYNC_16(dst, src) \
    asm volatile("cp.async.cg.shared.global [%0], [%1], 16;" :: "r"(dst), "l"(src))
#define CP_ASYNC_COMMIT() asm volatile("cp.async.commit_group;" ::: "memory")
#define CP_ASYNC_WAIT(n)  asm volatile("cp.async.wait_group %0;" :: "n"(n) : "memory")
#define LDSM4(r, a) \
    asm volatile("ldmatrix.sync.aligned.m8n8.x4.shared.b16 {%0,%1,%2,%3}, [%4];" \
        : "=r"((r)[0]), "=r"((r)[1]), "=r"((r)[2]), "=r"((r)[3]) : "r"(a))
#define MMA16816(d, a, b0, b1) \
    asm volatile("mma.sync.aligned.m16n8k16.row.col.f32.bf16.bf16.f32 " \
        "{%0,%1,%2,%3}, {%4,%5,%6,%7}, {%8,%9}, {%0,%1,%2,%3};" \
        : "+f"((d)[0]), "+f"((d)[1]), "+f"((d)[2]), "+f"((d)[3]) \
        : "r"((a)[0]), "r"((a)[1]), "r"((a)[2]), "r"((a)[3]), "r"(b0), "r"(b1))
#define MMAF8(d, a, b0, b1) \
    asm volatile("mma.sync.aligned.m16n8k32.row.col.f32.e4m3.e4m3.f32 " \
        "{%0,%1,%2,%3}, {%4,%5,%6,%7}, {%8,%9}, {%0,%1,%2,%3};" \
        : "+f"((d)[0]), "+f"((d)[1]), "+f"((d)[2]), "+f"((d)[3]) \
        : "r"((a)[0]), "r"((a)[1]), "r"((a)[2]), "r"((a)[3]), "r"(b0), "r"(b1))
__device__ __forceinline__ uint32_t sw64(uint32_t o) { return o ^ ((o >> 3) & 0x30); }

// ===========================================================================
// MAIN-PASS GEMM (bf16 hi x hi): C = Ah * Bh^T -> fp32
// 128x128 tile, BK=32, 6-stage pipeline (96KB), warp tile 64x32
// ===========================================================================
#define H_STAGES 6
#define H_TILE   8192                // 128 rows x 64B
#define H_STAGE  (2 * H_TILE)
#define H_SMEM   (H_STAGES * H_STAGE)   // 98304

struct LoaderH { const __nv_bfloat16 *pA, *pB; uint32_t d0, d1; int helem; };

__device__ __forceinline__ void load_stage_h(uint32_t sb, int st, const LoaderH& L, int k0)
{
    uint32_t stb = sb + st * H_STAGE;
    const __nv_bfloat16* a = L.pA + k0 + L.helem;
    const __nv_bfloat16* b = L.pB + k0 + L.helem;
    CP_ASYNC_16(stb + L.d0, a);            CP_ASYNC_16(stb + L.d1, a + 8);
    CP_ASYNC_16(stb + H_TILE + L.d0, b);   CP_ASYNC_16(stb + H_TILE + L.d1, b + 8);
    CP_ASYNC_COMMIT();
}

struct FragsH { uint32_t ah[4][4], bh[2][4]; };

__device__ __forceinline__ void load_frags_h(FragsH& f, uint32_t stb,
                                             uint32_t a_base, uint32_t b_base, int k16)
{
    #pragma unroll
    for (int mi = 0; mi < 4; ++mi) {
        const uint32_t off = a_base + (uint32_t)mi * 1024 + k16 * 32;
        LDSM4(f.ah[mi], stb + sw64(off));
    }
    #pragma unroll
    for (int ng = 0; ng < 2; ++ng) {
        const uint32_t off = b_base + (uint32_t)ng * 1024 + k16 * 32;
        LDSM4(f.bh[ng], stb + H_TILE + sw64(off));
    }
}

__device__ __forceinline__ void mma_group_h(float acc[4][4][4], const FragsH& f)
{
    #pragma unroll
    for (int mi = 0; mi < 4; ++mi)
        #pragma unroll
        for (int ni = 0; ni < 4; ++ni) {
            const int ng = ni >> 1, sel = (ni & 1) * 2;
            MMA16816(acc[mi][ni], f.ah[mi], f.bh[ng][sel], f.bh[ng][sel + 1]);
        }
}

__device__ __forceinline__ void gemm_core_h(
    const __nv_bfloat16* __restrict__ A, const __nv_bfloat16* __restrict__ B,
    float* __restrict__ Cf, int N, int K, int Ks, int bm, int bn)
{
    extern __shared__ __align__(1024) char smem[];
    const uint32_t sb = smem_u32(smem);
    const int tid = threadIdx.x, lane = tid & 31, wid = tid >> 5;
    const int wm = (wid & 1) * 64, wn = (wid >> 1) * 32;

    LoaderH L;
    {
        const int lrow = tid >> 1;
        const int lhalf = (tid & 1) * 32;
        uint32_t o = (uint32_t)lrow * 64 + lhalf;
        L.d0 = sw64(o); L.d1 = sw64(o + 16);
        L.helem = lhalf >> 1;
        L.pA = A + (size_t)(bm + lrow) * Ks;
        L.pB = B + (size_t)(bn + lrow) * Ks;
    }
    const uint32_t a_base = (uint32_t)(wm + (lane & 15)) * 64 + (lane >> 4) * 16;
    const uint32_t b_base = (uint32_t)(wn + (lane & 7) + ((lane >> 4) << 3)) * 64
                          + ((lane >> 3) & 1) * 16;

    float acc[4][4][4];
    #pragma unroll
    for (int i = 0; i < 4; ++i)
        #pragma unroll
        for (int j = 0; j < 4; ++j)
            #pragma unroll
            for (int r = 0; r < 4; ++r) acc[i][j][r] = 0.0f;

    const int nk = K / 32;
    #pragma unroll
    for (int s = 0; s < 5; ++s) load_stage_h(sb, s, L, s * 32);
    CP_ASYNC_WAIT(4);
    __syncthreads();

    FragsH fa, fb;
    load_frags_h(fa, sb, a_base, b_base, 0);

    int st = 0, stw = 5;
    for (int i = 0; i < nk; ++i) {
        const uint32_t stb = sb + st * H_STAGE;
        load_frags_h(fb, stb, a_base, b_base, 1);
        mma_group_h(acc, fa);
        if (i + 5 < nk) load_stage_h(sb, stw, L, (i + 5) * 32);
        else            CP_ASYNC_COMMIT();
        CP_ASYNC_WAIT(4);
        __syncthreads();
        if (++st  == H_STAGES) st  = 0;
        if (++stw == H_STAGES) stw = 0;
        if (i + 1 < nk) load_frags_h(fa, sb + st * H_STAGE, a_base, b_base, 0);
        mma_group_h(acc, fb);
    }

    const int er = lane >> 2, ec = (lane & 3) * 2;
    #pragma unroll
    for (int mi = 0; mi < 4; ++mi)
        #pragma unroll
        for (int ni = 0; ni < 4; ++ni) {
            const int r0 = bm + wm + mi * 16 + er;
            const int c0 = bn + wn + ni * 8 + ec;
            float* a = acc[mi][ni];
            *(float2*)(Cf + (size_t)r0 * N + c0)       = make_float2(a[0], a[1]);
            *(float2*)(Cf + (size_t)(r0 + 8) * N + c0) = make_float2(a[2], a[3]);
        }
}

// ===========================================================================
// CORRECTION GEMM (fp8): C = S * (Ah*Bl^T + Al*Bh^T) -> fp32 (scaled)
// fp8 tiles are byte-identical to bf16 tiles (64B rows); BK=64 fp8 elements.
// 5-stage pipeline (160KB), 2 fp8 passes per k32 step.
// ===========================================================================
#define C_STAGES 5
#define C_TILE   8192                // 128 rows x 64B (64 fp8)
#define C_OFF_AL C_TILE
#define C_OFF_BH (2 * C_TILE)
#define C_OFF_BL (3 * C_TILE)
#define C_STAGE  (4 * C_TILE)        // 32768
#define C_SMEM   (C_STAGES * C_STAGE)   // 163840

struct LoaderC { const uint8_t *pAh, *pAl, *pBh, *pBl; uint32_t d0, d1; int helem; };

__device__ __forceinline__ void load_stage_c(uint32_t sb, int st, const LoaderC& L, int k0)
{
    uint32_t stb = sb + st * C_STAGE;
    const uint8_t* a0 = L.pAh + k0 + L.helem;
    const uint8_t* a1 = L.pAl + k0 + L.helem;
    const uint8_t* b0 = L.pBh + k0 + L.helem;
    const uint8_t* b1 = L.pBl + k0 + L.helem;
    CP_ASYNC_16(stb + L.d0, a0);             CP_ASYNC_16(stb + L.d1, a0 + 16);
    CP_ASYNC_16(stb + C_OFF_AL + L.d0, a1);  CP_ASYNC_16(stb + C_OFF_AL + L.d1, a1 + 16);
    CP_ASYNC_16(stb + C_OFF_BH + L.d0, b0);  CP_ASYNC_16(stb + C_OFF_BH + L.d1, b0 + 16);
    CP_ASYNC_16(stb + C_OFF_BL + L.d0, b1);  CP_ASYNC_16(stb + C_OFF_BL + L.d1, b1 + 16);
    CP_ASYNC_COMMIT();
}

struct FragsC { uint32_t ah[4][4], al[4][4], bh[2][4], bl[2][4]; };

__device__ __forceinline__ void load_frags_c(FragsC& f, uint32_t stb,
                                             uint32_t a_base, uint32_t b_base, int s)
{
    #pragma unroll
    for (int mi = 0; mi < 4; ++mi) {
        const uint32_t off = a_base + (uint32_t)mi * 1024 + s * 32;
        LDSM4(f.ah[mi], stb + sw64(off));
        LDSM4(f.al[mi], stb + C_OFF_AL + sw64(off));
    }
    #pragma unroll
    for (int ng = 0; ng < 2; ++ng) {
        const uint32_t off = b_base + (uint32_t)ng * 1024 + s * 32;
        LDSM4(f.bh[ng], stb + C_OFF_BH + sw64(off));
        LDSM4(f.bl[ng], stb + C_OFF_BL + sw64(off));
    }
}

__device__ __forceinline__ void mma_group_c(float acc[4][4][4], const FragsC& f)
{
    #pragma unroll
    for (int mi = 0; mi < 4; ++mi)          // pass 1: A8h * B8l
        #pragma unroll
        for (int ni = 0; ni < 4; ++ni) {
            const int ng = ni >> 1, sel = (ni & 1) * 2;
            MMAF8(acc[mi][ni], f.ah[mi], f.bl[ng][sel], f.bl[ng][sel + 1]);
        }
    #pragma unroll
    for (int mi = 0; mi < 4; ++mi)          // pass 2: A8l * B8h
        #pragma unroll
        for (int ni = 0; ni < 4; ++ni) {
            const int ng = ni >> 1, sel = (ni & 1) * 2;
            MMAF8(acc[mi][ni], f.al[mi], f.bh[ng][sel], f.bh[ng][sel + 1]);
        }
}

__device__ __forceinline__ void gemm_core_c(
    const uint8_t* __restrict__ A8h, const uint8_t* __restrict__ A8l,
    const uint8_t* __restrict__ B8h, const uint8_t* __restrict__ B8l,
    float* __restrict__ Cf, int N, int K, int Ks, int bm, int bn)
{
    extern __shared__ __align__(1024) char smem[];
    const uint32_t sb = smem_u32(smem);
    const int tid = threadIdx.x, lane = tid & 31, wid = tid >> 5;
    const int wm = (wid & 1) * 64, wn = (wid >> 1) * 32;

    LoaderC L;
    {
        const int lrow = tid >> 1;
        const int lhalf = (tid & 1) * 32;   // bytes within 64B row
        uint32_t o = (uint32_t)lrow * 64 + lhalf;
        L.d0 = sw64(o); L.d1 = sw64(o + 16);
        L.helem = lhalf;
        L.pAh = A8h + (size_t)(bm + lrow) * Ks;
        L.pAl = A8l + (size_t)(bm + lrow) * Ks;
        L.pBh = B8h + (size_t)(bn + lrow) * Ks;
        L.pBl = B8l + (size_t)(bn + lrow) * Ks;
    }
    const uint32_t a_base = (uint32_t)(wm + (lane & 15)) * 64 + (lane >> 4) * 16;
    const uint32_t b_base = (uint32_t)(wn + (lane & 7) + ((lane >> 4) << 3)) * 64
                          + ((lane >> 3) & 1) * 16;

    float acc[4][4][4];
    #pragma unroll
    for (int i = 0; i < 4; ++i)
        #pragma unroll
        for (int j = 0; j < 4; ++j)
            #pragma unroll
            for (int r = 0; r < 4; ++r) acc[i][j][r] = 0.0f;

    const int nk = K / 64;          // 64 fp8 per iteration
    load_stage_c(sb, 0, L, 0);
    load_stage_c(sb, 1, L, 64);
    load_stage_c(sb, 2, L, 128);
    load_stage_c(sb, 3, L, 192);
    CP_ASYNC_WAIT(3);
    __syncthreads();

    FragsC fa, fb;
    load_frags_c(fa, sb, a_base, b_base, 0);

    int st = 0, stw = 4;
    for (int i = 0; i < nk; ++i) {
        const uint32_t stb = sb + st * C_STAGE;
        load_frags_c(fb, stb, a_base, b_base, 1);
        mma_group_c(acc, fa);
        if (i + 4 < nk) load_stage_c(sb, stw, L, (i + 4) * 64);
        else            CP_ASYNC_COMMIT();
        CP_ASYNC_WAIT(3);
        __syncthreads();
        if (++st  == C_STAGES) st  = 0;
        if (++stw == C_STAGES) stw = 0;
        if (i + 1 < nk) load_frags_c(fa, sb + st * C_STAGE, a_base, b_base, 0);
        mma_group_c(acc, fb);
    }

    const int er = lane >> 2, ec = (lane & 3) * 2;
    #pragma unroll
    for (int mi = 0; mi < 4; ++mi)
        #pragma unroll
        for (int ni = 0; ni < 4; ++ni) {
            const int r0 = bm + wm + mi * 16 + er;
            const int c0 = bn + wn + ni * 8 + ec;
            float* a = acc[mi][ni];
            *(float2*)(Cf + (size_t)r0 * N + c0)       = make_float2(a[0], a[1]);
            *(float2*)(Cf + (size_t)(r0 + 8) * N + c0) = make_float2(a[2], a[3]);
        }
}

// ===========================================================================
// GEMM driver kernels
// ===========================================================================
__global__ __launch_bounds__(256, 1)
void qkv_hh(const __nv_bfloat16* __restrict__ xh,
            const __nv_bfloat16* __restrict__ Wqh, const __nv_bfloat16* __restrict__ Wkh,
            const __nv_bfloat16* __restrict__ Wvh, float* __restrict__ p1)
{
    const int idx = blockIdx.x;
    if (idx < 1024) {
        const int j = idx & 511;
        const int bn = (j & 15) * 128, bm = (j >> 4) * 128;
        const __nv_bfloat16* B = (idx < 512) ? Wqh : Wkh;
        float* C = p1 + (idx < 512 ? 0 : SE);
        gemm_core_h(xh, B, C, E, E, E, bm, bn);
    } else {
        const int j = idx - 1024;
        const int bn = (j & 31) * 128, bm = (j >> 5) * 128;
        gemm_core_h(Wvh, xh, p1 + 2 * SE, SEQ, E, E, bm, bn);
    }
}

__global__ __launch_bounds__(256, 1)
void qkv_corr(const uint8_t* __restrict__ x8h, const uint8_t* __restrict__ x8l,
              const uint8_t* __restrict__ Wq8h, const uint8_t* __restrict__ Wq8l,
              const uint8_t* __restrict__ Wk8h, const uint8_t* __restrict__ Wk8l,
              const uint8_t* __restrict__ Wv8h, const uint8_t* __restrict__ Wv8l,
              float* __restrict__ p2)
{
    const int idx = blockIdx.x;
    if (idx < 1024) {
        const int j = idx & 511;
        const int bn = (j & 15) * 128, bm = (j >> 4) * 128;
        const uint8_t* Bh = (idx < 512) ? Wq8h : Wk8h;
        const uint8_t* Bl = (idx < 512) ? Wq8l : Wk8l;
        float* C = p2 + (idx < 512 ? 0 : SE);
        gemm_core_c(x8h, x8l, Bh, Bl, C, E, E, E, bm, bn);
    } else {
        const int j = idx - 1024;
        const int bn = (j & 31) * 128, bm = (j >> 5) * 128;
        gemm_core_c(Wv8h, Wv8l, x8h, x8l, p2 + 2 * SE, SEQ, E, E, bm, bn);
    }
}

__global__ __launch_bounds__(256, 1)
void s_hh(const __nv_bfloat16* __restrict__ qh, const __nv_bfloat16* __restrict__ kh,
          float* __restrict__ s1)
{
    gemm_core_h(qh, kh, s1, SEQ, E, E, blockIdx.y * 128, blockIdx.x * 128);
}

__global__ __launch_bounds__(256, 1)
void s_corr(const uint8_t* __restrict__ q8h, const uint8_t* __restrict__ q8l,
            const uint8_t* __restrict__ k8h, const uint8_t* __restrict__ k8l,
            float* __restrict__ s2)
{
    gemm_core_c(q8h, q8l, k8h, k8l, s2, SEQ, E, E, blockIdx.y * 128, blockIdx.x * 128);
}

// out main pass, split-K (2 halves -> disjoint fp32 partials in p1)
__global__ __launch_bounds__(256, 1)
void out_hh_sk(const __nv_bfloat16* __restrict__ wh, const __nv_bfloat16* __restrict__ vTh,
               float* __restrict__ p1)
{
    const int idx = blockIdx.x;
    const int h = idx >> 9;
    const int j = idx & 511;
    const int bn = (j & 15) * 128, bm = (j >> 4) * 128;
    const int koff = h * (SEQ / 2);
    gemm_core_h(wh + koff, vTh + koff, p1 + (size_t)h * SE, E, SEQ / 2, SEQ, bm, bn);
}

__global__ __launch_bounds__(256, 1)
void out_corr(const uint8_t* __restrict__ w8h, const uint8_t* __restrict__ w8l,
              const uint8_t* __restrict__ vT8h, const uint8_t* __restrict__ vT8l,
              float* __restrict__ p2)
{
    gemm_core_c(w8h, w8l, vT8h, vT8l, p2, E, SEQ, SEQ, blockIdx.y * 128, blockIdx.x * 128);
}

// ===========================================================================
// Elementwise kernels
// ===========================================================================
__device__ __forceinline__ uint32_t f8x4(float a, float b, float c, float d)
{
    uint32_t r =  (uint32_t)__nv_cvt_float_to_fp8(a, __NV_SATFINITE, __NV_E4M3);
    r |= (uint32_t)__nv_cvt_float_to_fp8(b, __NV_SATFINITE, __NV_E4M3) << 8;
    r |= (uint32_t)__nv_cvt_float_to_fp8(c, __NV_SATFINITE, __NV_E4M3) << 16;
    r |= (uint32_t)__nv_cvt_float_to_fp8(d, __NV_SATFINITE, __NV_E4M3) << 24;
    return r;
}

// split v -> bf16 hi + fp8(hi*Sh) + fp8((v-hi)*Sl), 4 elements at off4
__device__ __forceinline__ void split_store(float4 v, __nv_bfloat16* hi,
                                            uint8_t* h8, uint8_t* l8,
                                            int off4, float Sh, float Sl)
{
    __nv_bfloat16 h0 = __float2bfloat16(v.x), h1 = __float2bfloat16(v.y);
    __nv_bfloat16 h2 = __float2bfloat16(v.z), h3 = __float2bfloat16(v.w);
    float f0 = __bfloat162float(h0), f1 = __bfloat162float(h1);
    float f2 = __bfloat162float(h2), f3 = __bfloat162float(h3);
    ((__nv_bfloat162*)hi)[2 * off4]     = __halves2bfloat162(h0, h1);
    ((__nv_bfloat162*)hi)[2 * off4 + 1] = __halves2bfloat162(h2, h3);
    ((uint32_t*)h8)[off4] = f8x4(f0 * Sh, f1 * Sh, f2 * Sh, f3 * Sh);
    ((uint32_t*)l8)[off4] = f8x4((v.x - f0) * Sl, (v.y - f1) * Sl,
                                 (v.z - f2) * Sl, (v.w - f3) * Sl);
}

#define X4 (SE / 4)
#define W4 (EE / 4)

__global__ void conv_all(const float* __restrict__ x,  const float* __restrict__ Wq,
                         const float* __restrict__ Wk, const float* __restrict__ Wv)
{
    int i = blockIdx.x * blockDim.x + threadIdx.x;
    const float* src; __nv_bfloat16* hi; uint8_t *h8, *l8; int off; float Sh, Sl;
    if (i < X4)               { src = x;  hi = g_xh;  h8 = g_x8h;  l8 = g_x8l;  off = i;              Sh = 32.0f;   Sl = 16384.0f; }
    else if (i < X4 + W4)     { src = Wq; hi = g_Wqh; h8 = g_Wq8h; l8 = g_Wq8l; off = i - X4;         Sh = 1024.0f; Sl = 524288.0f; }
    else if (i < X4 + 2 * W4) { src = Wk; hi = g_Wkh; h8 = g_Wk8h; l8 = g_Wk8l; off = i - X4 - W4;    Sh = 1024.0f; Sl = 524288.0f; }
    else if (i < X4 + 3 * W4) { src = Wv; hi = g_Wvh; h8 = g_Wv8h; l8 = g_Wv8l; off = i - X4 - 2*W4;  Sh = 1024.0f; Sl = 524288.0f; }
    else return;
    split_store(((const float4*)src)[off], hi, h8, l8, off, Sh, Sl);
}

// combine qkv partials and emit bf16 hi + fp8 hi/lo (Sh=64, Sl=32768)
__global__ void combine_qkv(const float* __restrict__ p1, const float* __restrict__ p2)
{
    int i = blockIdx.x * blockDim.x + threadIdx.x;
    const int n4 = SE / 4;
    if (i >= 3 * n4) return;
    float4 a = ((const float4*)p1)[i];
    float4 b = ((const float4*)p2)[i];
    float4 v = make_float4(a.x + b.x * INV_QKV, a.y + b.y * INV_QKV,
                           a.z + b.z * INV_QKV, a.w + b.w * INV_QKV);
    if (i < n4)          split_store(v, g_qh,  g_q8h,  g_q8l,  i,          64.0f, 32768.0f);
    else if (i < 2 * n4) split_store(v, g_kh,  g_k8h,  g_k8l,  i - n4,     64.0f, 32768.0f);
    else                 split_store(v, g_vTh, g_vT8h, g_vT8l, i - 2 * n4, 64.0f, 32768.0f);
}

// ---------------------------------------------------------------------------
// Row softmax: reads two s partials, emits w as bf16 hi + fp8 hi/lo
// (Sh=256, Sl=131072)
// ---------------------------------------------------------------------------
__inline__ __device__ float warp_max(float v) {
    #pragma unroll
    for (int o = 16; o > 0; o >>= 1) v = fmaxf(v, __shfl_xor_sync(0xffffffffu, v, o));
    return v;
}
__inline__ __device__ float warp_sum(float v) {
    #pragma unroll
    for (int o = 16; o > 0; o >>= 1) v += __shfl_xor_sync(0xffffffffu, v, o);
    return v;
}

__global__ __launch_bounds__(256)
void softmax_rows(const float* __restrict__ S1, const float* __restrict__ S2)
{
    const int rowi = blockIdx.x;
    const float4* p1 = (const float4*)(S1 + (size_t)rowi * SEQ);
    const float4* p2 = (const float4*)(S2 + (size_t)rowi * SEQ);
    const float scale = 0.022097086912079608f;  // 1/sqrt(2048)
    const int tid = threadIdx.x, lane = tid & 31, wid = tid >> 5;

    __shared__ float red[8];

    float4 v[4];
    float m = -1e30f;
    #pragma unroll
    for (int i = 0; i < 4; ++i) {
        float4 a = p1[tid + i * 256];
        float4 b = p2[tid + i * 256];
        v[i] = make_float4((a.x + b.x * INV_S) * scale, (a.y + b.y * INV_S) * scale,
                           (a.z + b.z * INV_S) * scale, (a.w + b.w * INV_S) * scale);
        m = fmaxf(m, fmaxf(fmaxf(v[i].x, v[i].y), fmaxf(v[i].z, v[i].w)));
    }
    m = warp_max(m);
    if (lane == 0) red[wid] = m;
    __syncthreads();
    if (wid == 0) {
        float t = (lane < 8) ? red[lane] : -1e30f;
        t = warp_max(t);
        if (lane == 0) red[0] = t;
    }
    __syncthreads();
    m = red[0];
    __syncthreads();

    float sum = 0.0f;
    #pragma unroll
    for (int i = 0; i < 4; ++i) {
        v[i].x = __expf(v[i].x - m);  v[i].y = __expf(v[i].y - m);
        v[i].z = __expf(v[i].z - m);  v[i].w = __expf(v[i].w - m);
        sum += (v[i].x + v[i].y) + (v[i].z + v[i].w);
    }
    sum = warp_sum(sum);
    if (lane == 0) red[wid] = sum;
    __syncthreads();
    if (wid == 0) {
        float t = (lane < 8) ? red[lane] : 0.0f;
        t = warp_sum(t);
        if (lane == 0) red[0] = t;
    }
    __syncthreads();
    const float inv = 1.0f / red[0];

    #pragma unroll
    for (int i = 0; i < 4; ++i) {
        const int off4 = (int)((size_t)rowi * SEQ / 4) + tid + i * 256;
        float4 w = make_float4(v[i].x * inv, v[i].y * inv, v[i].z * inv, v[i].w * inv);
        split_store(w, g_wh, g_w8h, g_w8l, off4, 256.0f, 131072.0f);
    }
}

// final: out = p1[half0] + p1[half1] + p2/2^23
__global__ void reduce_out(const float* __restrict__ p1, const float* __restrict__ p2,
                           float* __restrict__ out)
{
    int i = blockIdx.x * blockDim.x + threadIdx.x;
    const int n4 = SE / 4;
    if (i >= n4) return;
    float4 a = ((const float4*)p1)[i];
    float4 b = ((const float4*)p1)[i + n4];
    float4 c = ((const float4*)p2)[i];
    ((float4*)out)[i] = make_float4(a.x + b.x + c.x * INV_OUT,
                                    a.y + b.y + c.y * INV_OUT,
                                    a.z + b.z + c.z * INV_OUT,
                                    a.w + b.w + c.w * INV_OUT);
}

// ===========================================================================
// kernel_launch
// ===========================================================================
extern "C" void kernel_launch(void* const* d_in, const int* in_sizes, int n_in,
                              void* d_out, int out_size)
{
    const float* x  = (const float*)d_in[0];
    const float* Wq = (const float*)d_in[1];
    const float* Wk = (const float*)d_in[2];
    const float* Wv = (const float*)d_in[3];
    float* out = (float*)d_out;

    cudaFuncSetAttribute(qkv_hh,    cudaFuncAttributeMaxDynamicSharedMemorySize, H_SMEM);
    cudaFuncSetAttribute(s_hh,      cudaFuncAttributeMaxDynamicSharedMemorySize, H_SMEM);
    cudaFuncSetAttribute(out_hh_sk, cudaFuncAttributeMaxDynamicSharedMemorySize, H_SMEM);
    cudaFuncSetAttribute(qkv_corr,  cudaFuncAttributeMaxDynamicSharedMemorySize, C_SMEM);
    cudaFuncSetAttribute(s_corr,    cudaFuncAttributeMaxDynamicSharedMemorySize, C_SMEM);
    cudaFuncSetAttribute(out_corr,  cudaFuncAttributeMaxDynamicSharedMemorySize, C_SMEM);

    __nv_bfloat16 *xh, *Wqh, *Wkh, *Wvh, *qh, *kh, *vTh, *wh;
    uint8_t *x8h, *x8l, *Wq8h, *Wq8l, *Wk8h, *Wk8l, *Wv8h, *Wv8l;
    uint8_t *q8h, *q8l, *k8h, *k8l, *vT8h, *vT8l, *w8h, *w8l;
    float *p1, *p2, *s1, *s2;
    cudaGetSymbolAddress((void**)&xh, g_xh);   cudaGetSymbolAddress((void**)&Wqh, g_Wqh);
    cudaGetSymbolAddress((void**)&Wkh, g_Wkh); cudaGetSymbolAddress((void**)&Wvh, g_Wvh);
    cudaGetSymbolAddress((void**)&qh, g_qh);   cudaGetSymbolAddress((void**)&kh, g_kh);
    cudaGetSymbolAddress((void**)&vTh, g_vTh); cudaGetSymbolAddress((void**)&wh, g_wh);
    cudaGetSymbolAddress((void**)&x8h, g_x8h); cudaGetSymbolAddress((void**)&x8l, g_x8l);
    cudaGetSymbolAddress((void**)&Wq8h, g_Wq8h); cudaGetSymbolAddress((void**)&Wq8l, g_Wq8l);
    cudaGetSymbolAddress((void**)&Wk8h, g_Wk8h); cudaGetSymbolAddress((void**)&Wk8l, g_Wk8l);
    cudaGetSymbolAddress((void**)&Wv8h, g_Wv8h); cudaGetSymbolAddress((void**)&Wv8l, g_Wv8l);
    cudaGetSymbolAddress((void**)&q8h, g_q8h); cudaGetSymbolAddress((void**)&q8l, g_q8l);
    cudaGetSymbolAddress((void**)&k8h, g_k8h); cudaGetSymbolAddress((void**)&k8l, g_k8l);
    cudaGetSymbolAddress((void**)&vT8h, g_vT8h); cudaGetSymbolAddress((void**)&vT8l, g_vT8l);
    cudaGetSymbolAddress((void**)&w8h, g_w8h); cudaGetSymbolAddress((void**)&w8l, g_w8l);
    cudaGetSymbolAddress((void**)&p1, g_p1);   cudaGetSymbolAddress((void**)&p2, g_p2);
    cudaGetSymbolAddress((void**)&s1, g_s);    cudaGetSymbolAddress((void**)&s2, g_s2);

    // 1. split inputs: bf16 hi + fp8 hi/lo
    const int total4 = X4 + 3 * W4;
    conv_all<<<(total4 + 255) / 256, 256>>>(x, Wq, Wk, Wv);

    // 2-3. qkv: main bf16 pass + fp8 correction pass
    qkv_hh  <<<1536, 256, H_SMEM>>>(xh, Wqh, Wkh, Wvh, p1);
    qkv_corr<<<1536, 256, C_SMEM>>>(x8h, x8l, Wq8h, Wq8l, Wk8h, Wk8l, Wv8h, Wv8l, p2);

    // 4. combine -> q,k,vT (bf16 hi + fp8 hi/lo)
    combine_qkv<<<(3 * (SE / 4) + 255) / 256, 256>>>(p1, p2);

    // 5-6. s = q k^T: main + correction partials
    s_hh  <<<dim3(SEQ / 128, SEQ / 128), 256, H_SMEM>>>(qh, kh, s1);
    s_corr<<<dim3(SEQ / 128, SEQ / 128), 256, C_SMEM>>>(q8h, q8l, k8h, k8l, s2);

    // 7. softmax (combines partials) -> w (bf16 hi + fp8 hi/lo)
    softmax_rows<<<SEQ, 256>>>(s1, s2);

    // 8-9. out = w vT^T: split-K main pass + correction pass
    out_hh_sk<<<1024, 256, H_SMEM>>>(wh, vTh, p1);
    out_corr <<<dim3(E / 128, SEQ / 128), 256, C_SMEM>>>(w8h, w8l, vT8h, vT8l, p2);

    // 10. final combine
    reduce_out<<<(SE / 4 + 255) / 256, 256>>>(p1, p2, out);
}

// round 13
// speedup vs baseline: 1.8257x; 1.8257x over previous
#include <cuda_runtime.h>
#include <cuda_bf16.h>
#include <cuda_fp16.h>
#include <stdint.h>

#define SEQ 4096
#define E   2048
#define SE  (SEQ * E)
#define EE  (E * E)
#define SS  ((size_t)SEQ * SEQ)

// ---------------------------------------------------------------------------
// Scratch (__device__ globals per allocation-free rule)
// g_s: s logits (fp32) before softmax, then split-K partials for out-GEMM.
// ---------------------------------------------------------------------------
__device__ __half g_xh [SE], g_xl [SE];
__device__ __half g_Wqh[EE], g_Wql[EE];
__device__ __half g_Wkh[EE], g_Wkl[EE];
__device__ __half g_Wvh[EE], g_Wvl[EE];
__device__ __half g_qh [SE];                 // A-side of s-GEMM: hi only
__device__ __half g_kh [SE], g_kl [SE];
__device__ __half g_vTh[SE], g_vTl[SE];
__device__ __half g_wh [SS];                 // A-side of out-GEMM: hi only
__device__ float  g_s  [SS];

// ---------------------------------------------------------------------------
// PTX helpers
// ---------------------------------------------------------------------------
__device__ __forceinline__ uint32_t smem_u32(const void* p) {
    uint32_t a;
    asm("{ .reg .u64 t; cvta.to.shared.u64 t, %1; cvt.u32.u64 %0, t; }" : "=r"(a) : "l"(p));
    return a;
}
#define CP_ASYNC_16(dst, src) \
    asm volatile("cp.async.cg.shared.global [%0], [%1], 16;" :: "r"(dst), "l"(src))
#define CP_ASYNC_COMMIT() asm volatile("cp.async.commit_group;" ::: "memory")
#define CP_ASYNC_WAIT(n)  asm volatile("cp.async.wait_group %0;" :: "n"(n) : "memory")
#define LDSM4(r, a) \
    asm volatile("ldmatrix.sync.aligned.m8n8.x4.shared.b16 {%0,%1,%2,%3}, [%4];" \
        : "=r"((r)[0]), "=r"((r)[1]), "=r"((r)[2]), "=r"((r)[3]) : "r"(a))
#define MMAH(d, a, b0, b1) \
    asm volatile("mma.sync.aligned.m16n8k16.row.col.f32.f16.f16.f32 " \
        "{%0,%1,%2,%3}, {%4,%5,%6,%7}, {%8,%9}, {%0,%1,%2,%3};" \
        : "+f"((d)[0]), "+f"((d)[1]), "+f"((d)[2]), "+f"((d)[3]) \
        : "r"((a)[0]), "r"((a)[1]), "r"((a)[2]), "r"((a)[3]), "r"(b0), "r"(b1))
__device__ __forceinline__ uint32_t sw64(uint32_t o) { return o ^ ((o >> 3) & 0x30); }

// ===========================================================================
// CORE3 (fp16 x3, QKV): C = (Ah+Al)(Bh+Bl)^T minus AlBl  -> fp16 hi(+lo)
// 128x128 tile, BK=32, 5-stage (160KB), warp tile 64x32, pass-major order.
// ===========================================================================
#define TILE_B   8192                 // 128 rows x 64B
#define ST3_AL   TILE_B
#define ST3_BH   (2 * TILE_B)
#define ST3_BL   (3 * TILE_B)
#define STAGE3   (4 * TILE_B)         // 32768
#define SMEM3    (5 * STAGE3)         // 163840

struct Ld3 { const __half *pAh, *pAl, *pBh, *pBl; uint32_t d0, d1; int he; };

__device__ __forceinline__ void load_stage3(uint32_t sb, int st, const Ld3& L, int k0)
{
    uint32_t s = sb + st * STAGE3;
    const __half* a0 = L.pAh + k0 + L.he;
    const __half* a1 = L.pAl + k0 + L.he;
    const __half* b0 = L.pBh + k0 + L.he;
    const __half* b1 = L.pBl + k0 + L.he;
    CP_ASYNC_16(s + L.d0, a0);            CP_ASYNC_16(s + L.d1, a0 + 8);
    CP_ASYNC_16(s + ST3_AL + L.d0, a1);   CP_ASYNC_16(s + ST3_AL + L.d1, a1 + 8);
    CP_ASYNC_16(s + ST3_BH + L.d0, b0);   CP_ASYNC_16(s + ST3_BH + L.d1, b0 + 8);
    CP_ASYNC_16(s + ST3_BL + L.d0, b1);   CP_ASYNC_16(s + ST3_BL + L.d1, b1 + 8);
    CP_ASYNC_COMMIT();
}

struct Fr3 { uint32_t ah[4][4], al[4][4], bh[2][4], bl[2][4]; };

__device__ __forceinline__ void load_frags3(Fr3& f, uint32_t stb,
                                            uint32_t ab, uint32_t bb, int k16)
{
    #pragma unroll
    for (int mi = 0; mi < 4; ++mi) {
        const uint32_t off = ab + (uint32_t)mi * 1024 + k16 * 32;
        LDSM4(f.ah[mi], stb + sw64(off));
        LDSM4(f.al[mi], stb + ST3_AL + sw64(off));
    }
    #pragma unroll
    for (int ng = 0; ng < 2; ++ng) {
        const uint32_t off = bb + (uint32_t)ng * 1024 + k16 * 32;
        LDSM4(f.bh[ng], stb + ST3_BH + sw64(off));
        LDSM4(f.bl[ng], stb + ST3_BL + sw64(off));
    }
}

__device__ __forceinline__ void mma_group3(float acc[4][4][4], const Fr3& f)
{
    #pragma unroll
    for (int mi = 0; mi < 4; ++mi)
        #pragma unroll
        for (int ni = 0; ni < 4; ++ni) {
            const int ng = ni >> 1, sel = (ni & 1) * 2;
            MMAH(acc[mi][ni], f.ah[mi], f.bh[ng][sel], f.bh[ng][sel + 1]);
        }
    #pragma unroll
    for (int mi = 0; mi < 4; ++mi)
        #pragma unroll
        for (int ni = 0; ni < 4; ++ni) {
            const int ng = ni >> 1, sel = (ni & 1) * 2;
            MMAH(acc[mi][ni], f.ah[mi], f.bl[ng][sel], f.bl[ng][sel + 1]);
        }
    #pragma unroll
    for (int mi = 0; mi < 4; ++mi)
        #pragma unroll
        for (int ni = 0; ni < 4; ++ni) {
            const int ng = ni >> 1, sel = (ni & 1) * 2;
            MMAH(acc[mi][ni], f.al[mi], f.bh[ng][sel], f.bh[ng][sel + 1]);
        }
}

__device__ __forceinline__ void gemm_core3(
    const __half* __restrict__ Ah, const __half* __restrict__ Al,
    const __half* __restrict__ Bh, const __half* __restrict__ Bl,
    __half* __restrict__ Ch, __half* __restrict__ Cl,
    int N, int K, int bm, int bn)
{
    extern __shared__ __align__(1024) char smem[];
    const uint32_t sb = smem_u32(smem);
    const int tid = threadIdx.x, lane = tid & 31, wid = tid >> 5;
    const int wm = (wid & 1) * 64, wn = (wid >> 1) * 32;

    Ld3 L;
    {
        const int lrow = tid >> 1, lhalf = (tid & 1) * 32;
        uint32_t o = (uint32_t)lrow * 64 + lhalf;
        L.d0 = sw64(o); L.d1 = sw64(o + 16); L.he = lhalf >> 1;
        L.pAh = Ah + (size_t)(bm + lrow) * K;
        L.pAl = Al + (size_t)(bm + lrow) * K;
        L.pBh = Bh + (size_t)(bn + lrow) * K;
        L.pBl = Bl + (size_t)(bn + lrow) * K;
    }
    const uint32_t ab = (uint32_t)(wm + (lane & 15)) * 64 + (lane >> 4) * 16;
    const uint32_t bb = (uint32_t)(wn + (lane & 7) + ((lane >> 4) << 3)) * 64
                      + ((lane >> 3) & 1) * 16;

    float acc[4][4][4];
    #pragma unroll
    for (int i = 0; i < 4; ++i)
        #pragma unroll
        for (int j = 0; j < 4; ++j)
            #pragma unroll
            for (int r = 0; r < 4; ++r) acc[i][j][r] = 0.0f;

    const int nk = K / 32;
    #pragma unroll
    for (int s = 0; s < 4; ++s) load_stage3(sb, s, L, s * 32);
    CP_ASYNC_WAIT(3);
    __syncthreads();

    Fr3 fa, fb;
    load_frags3(fa, sb, ab, bb, 0);

    int st = 0, stw = 4;
    for (int i = 0; i < nk; ++i) {
        const uint32_t stb = sb + st * STAGE3;
        load_frags3(fb, stb, ab, bb, 1);
        mma_group3(acc, fa);
        if (i + 4 < nk) load_stage3(sb, stw, L, (i + 4) * 32);
        else            CP_ASYNC_COMMIT();
        CP_ASYNC_WAIT(3);
        __syncthreads();
        if (++st  == 5) st  = 0;
        if (++stw == 5) stw = 0;
        if (i + 1 < nk) load_frags3(fa, sb + st * STAGE3, ab, bb, 0);
        mma_group3(acc, fb);
    }

    const int er = lane >> 2, ec = (lane & 3) * 2;
    #pragma unroll
    for (int mi = 0; mi < 4; ++mi)
        #pragma unroll
        for (int ni = 0; ni < 4; ++ni) {
            const int r0 = bm + wm + mi * 16 + er;
            const int c0 = bn + wn + ni * 8 + ec;
            float* a = acc[mi][ni];
            #pragma unroll
            for (int h = 0; h < 2; ++h) {
                float v0 = a[2 * h], v1 = a[2 * h + 1];
                __half h0 = __float2half(v0), h1 = __float2half(v1);
                size_t off = (size_t)(r0 + 8 * h) * N + c0;
                *(__half2*)(Ch + off) = __halves2half2(h0, h1);
                if (Cl) {
                    __half l0 = __float2half(v0 - __half2float(h0));
                    __half l1 = __float2half(v1 - __half2float(h1));
                    *(__half2*)(Cl + off) = __halves2half2(l0, l1);
                }
            }
        }
}

// ===========================================================================
// CORE2 (fp16 x2, s & out): C = Ah*(Bh+Bl)^T -> fp32
// 3 tiles/stage (24KB), 5 stages (120KB). Better MMA:LDSM ratio (4:1).
// ===========================================================================
#define ST2_BH   TILE_B
#define ST2_BL   (2 * TILE_B)
#define STAGE2   (3 * TILE_B)         // 24576
#define SMEM2    (5 * STAGE2)         // 122880

struct Ld2 { const __half *pA, *pBh, *pBl; uint32_t d0, d1; int he; };

__device__ __forceinline__ void load_stage2(uint32_t sb, int st, const Ld2& L, int k0)
{
    uint32_t s = sb + st * STAGE2;
    const __half* a  = L.pA  + k0 + L.he;
    const __half* b0 = L.pBh + k0 + L.he;
    const __half* b1 = L.pBl + k0 + L.he;
    CP_ASYNC_16(s + L.d0, a);             CP_ASYNC_16(s + L.d1, a + 8);
    CP_ASYNC_16(s + ST2_BH + L.d0, b0);   CP_ASYNC_16(s + ST2_BH + L.d1, b0 + 8);
    CP_ASYNC_16(s + ST2_BL + L.d0, b1);   CP_ASYNC_16(s + ST2_BL + L.d1, b1 + 8);
    CP_ASYNC_COMMIT();
}

struct Fr2 { uint32_t ah[4][4], bh[2][4], bl[2][4]; };

__device__ __forceinline__ void load_frags2(Fr2& f, uint32_t stb,
                                            uint32_t ab, uint32_t bb, int k16)
{
    #pragma unroll
    for (int mi = 0; mi < 4; ++mi) {
        const uint32_t off = ab + (uint32_t)mi * 1024 + k16 * 32;
        LDSM4(f.ah[mi], stb + sw64(off));
    }
    #pragma unroll
    for (int ng = 0; ng < 2; ++ng) {
        const uint32_t off = bb + (uint32_t)ng * 1024 + k16 * 32;
        LDSM4(f.bh[ng], stb + ST2_BH + sw64(off));
        LDSM4(f.bl[ng], stb + ST2_BL + sw64(off));
    }
}

__device__ __forceinline__ void mma_group2(float acc[4][4][4], const Fr2& f)
{
    #pragma unroll
    for (int mi = 0; mi < 4; ++mi)
        #pragma unroll
        for (int ni = 0; ni < 4; ++ni) {
            const int ng = ni >> 1, sel = (ni & 1) * 2;
            MMAH(acc[mi][ni], f.ah[mi], f.bh[ng][sel], f.bh[ng][sel + 1]);
        }
    #pragma unroll
    for (int mi = 0; mi < 4; ++mi)
        #pragma unroll
        for (int ni = 0; ni < 4; ++ni) {
            const int ng = ni >> 1, sel = (ni & 1) * 2;
            MMAH(acc[mi][ni], f.ah[mi], f.bl[ng][sel], f.bl[ng][sel + 1]);
        }
}

__device__ __forceinline__ void gemm_core2(
    const __half* __restrict__ A,
    const __half* __restrict__ Bh, const __half* __restrict__ Bl,
    float* __restrict__ Cf, int N, int K, int Ks, int bm, int bn)
{
    extern __shared__ __align__(1024) char smem[];
    const uint32_t sb = smem_u32(smem);
    const int tid = threadIdx.x, lane = tid & 31, wid = tid >> 5;
    const int wm = (wid & 1) * 64, wn = (wid >> 1) * 32;

    Ld2 L;
    {
        const int lrow = tid >> 1, lhalf = (tid & 1) * 32;
        uint32_t o = (uint32_t)lrow * 64 + lhalf;
        L.d0 = sw64(o); L.d1 = sw64(o + 16); L.he = lhalf >> 1;
        L.pA  = A  + (size_t)(bm + lrow) * Ks;
        L.pBh = Bh + (size_t)(bn + lrow) * Ks;
        L.pBl = Bl + (size_t)(bn + lrow) * Ks;
    }
    const uint32_t ab = (uint32_t)(wm + (lane & 15)) * 64 + (lane >> 4) * 16;
    const uint32_t bb = (uint32_t)(wn + (lane & 7) + ((lane >> 4) << 3)) * 64
                      + ((lane >> 3) & 1) * 16;

    float acc[4][4][4];
    #pragma unroll
    for (int i = 0; i < 4; ++i)
        #pragma unroll
        for (int j = 0; j < 4; ++j)
            #pragma unroll
            for (int r = 0; r < 4; ++r) acc[i][j][r] = 0.0f;

    const int nk = K / 32;
    #pragma unroll
    for (int s = 0; s < 4; ++s) load_stage2(sb, s, L, s * 32);
    CP_ASYNC_WAIT(3);
    __syncthreads();

    Fr2 fa, fb;
    load_frags2(fa, sb, ab, bb, 0);

    int st = 0, stw = 4;
    for (int i = 0; i < nk; ++i) {
        const uint32_t stb = sb + st * STAGE2;
        load_frags2(fb, stb, ab, bb, 1);
        mma_group2(acc, fa);
        if (i + 4 < nk) load_stage2(sb, stw, L, (i + 4) * 32);
        else            CP_ASYNC_COMMIT();
        CP_ASYNC_WAIT(3);
        __syncthreads();
        if (++st  == 5) st  = 0;
        if (++stw == 5) stw = 0;
        if (i + 1 < nk) load_frags2(fa, sb + st * STAGE2, ab, bb, 0);
        mma_group2(acc, fb);
    }

    const int er = lane >> 2, ec = (lane & 3) * 2;
    #pragma unroll
    for (int mi = 0; mi < 4; ++mi)
        #pragma unroll
        for (int ni = 0; ni < 4; ++ni) {
            const int r0 = bm + wm + mi * 16 + er;
            const int c0 = bn + wn + ni * 8 + ec;
            float* a = acc[mi][ni];
            *(float2*)(Cf + (size_t)r0 * N + c0)       = make_float2(a[0], a[1]);
            *(float2*)(Cf + (size_t)(r0 + 8) * N + c0) = make_float2(a[2], a[3]);
        }
}

// ===========================================================================
// Driver kernels
// ===========================================================================
// Merged QKV (1536 CTAs, core3): q -> hi only; k, vT -> hi+lo.
__global__ __launch_bounds__(256, 1)
void qkv_gemm(const __half* __restrict__ xh,  const __half* __restrict__ xl,
              const __half* __restrict__ Wqh, const __half* __restrict__ Wql,
              const __half* __restrict__ Wkh, const __half* __restrict__ Wkl,
              const __half* __restrict__ Wvh, const __half* __restrict__ Wvl,
              __half* __restrict__ qh,
              __half* __restrict__ kh,  __half* __restrict__ kl,
              __half* __restrict__ vTh, __half* __restrict__ vTl)
{
    const int idx = blockIdx.x;
    if (idx < 1024) {
        const int j = idx & 511;
        const int bn = (j & 15) * 128, bm = (j >> 4) * 128;
        if (idx < 512)
            gemm_core3(xh, xl, Wqh, Wql, qh, nullptr, E, E, bm, bn);
        else
            gemm_core3(xh, xl, Wkh, Wkl, kh, kl, E, E, bm, bn);
    } else {
        const int j = idx - 1024;
        const int bn = (j & 31) * 128, bm = (j >> 5) * 128;
        gemm_core3(Wvh, Wvl, xh, xl, vTh, vTl, SEQ, E, bm, bn);
    }
}

// s = q @ k^T (core2): A = q hi, B = k hi+lo -> fp32
__global__ __launch_bounds__(256, 1)
void s_gemm(const __half* __restrict__ qh,
            const __half* __restrict__ kh, const __half* __restrict__ kl,
            float* __restrict__ s)
{
    gemm_core2(qh, kh, kl, s, SEQ, E, E, blockIdx.y * 128, blockIdx.x * 128);
}

// out = w @ vT^T, split-K (core2, 1024 CTAs): disjoint fp32 partials
__global__ __launch_bounds__(256, 1)
void out_gemm_sk(const __half* __restrict__ wh,
                 const __half* __restrict__ vTh, const __half* __restrict__ vTl,
                 float* __restrict__ part)
{
    const int idx = blockIdx.x;
    const int h = idx >> 9;
    const int j = idx & 511;
    const int bn = (j & 15) * 128, bm = (j >> 4) * 128;
    const int koff = h * (SEQ / 2);
    gemm_core2(wh + koff, vTh + koff, vTl + koff,
               part + (size_t)h * SE, E, SEQ / 2, SEQ, bm, bn);
}

__global__ void reduce_add(const float* __restrict__ part, float* __restrict__ out, int n4)
{
    int i = blockIdx.x * blockDim.x + threadIdx.x;
    if (i >= n4) return;
    float4 a = ((const float4*)part)[i];
    float4 b = ((const float4*)part)[i + n4];
    ((float4*)out)[i] = make_float4(a.x + b.x, a.y + b.y, a.z + b.z, a.w + b.w);
}

// ===========================================================================
// Elementwise
// ===========================================================================
#define X4 (SE / 4)
#define W4 (EE / 4)

__global__ void conv_all(const float* __restrict__ x,  const float* __restrict__ Wq,
                         const float* __restrict__ Wk, const float* __restrict__ Wv,
                         __half* __restrict__ xh,  __half* __restrict__ xl,
                         __half* __restrict__ Wqh, __half* __restrict__ Wql,
                         __half* __restrict__ Wkh, __half* __restrict__ Wkl,
                         __half* __restrict__ Wvh, __half* __restrict__ Wvl)
{
    int i = blockIdx.x * blockDim.x + threadIdx.x;
    const float* src; __half *hi, *lo; int off;
    if (i < X4)               { src = x;  hi = xh;  lo = xl;  off = i; }
    else if (i < X4 + W4)     { src = Wq; hi = Wqh; lo = Wql; off = i - X4; }
    else if (i < X4 + 2 * W4) { src = Wk; hi = Wkh; lo = Wkl; off = i - X4 - W4; }
    else if (i < X4 + 3 * W4) { src = Wv; hi = Wvh; lo = Wvl; off = i - X4 - 2 * W4; }
    else return;

    float4 v = ((const float4*)src)[off];
    __half h0 = __float2half(v.x), h1 = __float2half(v.y);
    __half h2 = __float2half(v.z), h3 = __float2half(v.w);
    __half l0 = __float2half(v.x - __half2float(h0));
    __half l1 = __float2half(v.y - __half2float(h1));
    __half l2 = __float2half(v.z - __half2float(h2));
    __half l3 = __float2half(v.w - __half2float(h3));
    ((__half2*)hi)[2 * off]     = __halves2half2(h0, h1);
    ((__half2*)hi)[2 * off + 1] = __halves2half2(h2, h3);
    ((__half2*)lo)[2 * off]     = __halves2half2(l0, l1);
    ((__half2*)lo)[2 * off + 1] = __halves2half2(l2, l3);
}

// ---------------------------------------------------------------------------
// Row softmax: fp32 in (float4), fp16 hi out, scale fused
// ---------------------------------------------------------------------------
__inline__ __device__ float warp_max(float v) {
    #pragma unroll
    for (int o = 16; o > 0; o >>= 1) v = fmaxf(v, __shfl_xor_sync(0xffffffffu, v, o));
    return v;
}
__inline__ __device__ float warp_sum(float v) {
    #pragma unroll
    for (int o = 16; o > 0; o >>= 1) v += __shfl_xor_sync(0xffffffffu, v, o);
    return v;
}

__global__ __launch_bounds__(256)
void softmax_rows(const float* __restrict__ S, __half* __restrict__ Wh)
{
    const int rowi = blockIdx.x;
    const float4* p4 = (const float4*)(S + (size_t)rowi * SEQ);
    const float scale = 0.022097086912079608f;  // 1/sqrt(2048)
    const int tid = threadIdx.x, lane = tid & 31, wid = tid >> 5;

    __shared__ float red[8];

    float4 v[4];
    float m = -1e30f;
    #pragma unroll
    for (int i = 0; i < 4; ++i) {
        float4 t = p4[tid + i * 256];
        v[i] = make_float4(t.x * scale, t.y * scale, t.z * scale, t.w * scale);
        m = fmaxf(m, fmaxf(fmaxf(v[i].x, v[i].y), fmaxf(v[i].z, v[i].w)));
    }
    m = warp_max(m);
    if (lane == 0) red[wid] = m;
    __syncthreads();
    if (wid == 0) {
        float t = (lane < 8) ? red[lane] : -1e30f;
        t = warp_max(t);
        if (lane == 0) red[0] = t;
    }
    __syncthreads();
    m = red[0];
    __syncthreads();

    float sum = 0.0f;
    #pragma unroll
    for (int i = 0; i < 4; ++i) {
        v[i].x = __expf(v[i].x - m);  v[i].y = __expf(v[i].y - m);
        v[i].z = __expf(v[i].z - m);  v[i].w = __expf(v[i].w - m);
        sum += (v[i].x + v[i].y) + (v[i].z + v[i].w);
    }
    sum = warp_sum(sum);
    if (lane == 0) red[wid] = sum;
    __syncthreads();
    if (wid == 0) {
        float t = (lane < 8) ? red[lane] : 0.0f;
        t = warp_sum(t);
        if (lane == 0) red[0] = t;
    }
    __syncthreads();
    const float inv = 1.0f / red[0];

    #pragma unroll
    for (int i = 0; i < 4; ++i) {
        const size_t base = (size_t)rowi * SEQ + (size_t)(tid + i * 256) * 4;
        __half h0 = __float2half(v[i].x * inv), h1 = __float2half(v[i].y * inv);
        __half h2 = __float2half(v[i].z * inv), h3 = __float2half(v[i].w * inv);
        *(__half2*)(Wh + base)     = __halves2half2(h0, h1);
        *(__half2*)(Wh + base + 2) = __halves2half2(h2, h3);
    }
}

// ===========================================================================
// kernel_launch
// ===========================================================================
extern "C" void kernel_launch(void* const* d_in, const int* in_sizes, int n_in,
                              void* d_out, int out_size)
{
    const float* x  = (const float*)d_in[0];
    const float* Wq = (const float*)d_in[1];
    const float* Wk = (const float*)d_in[2];
    const float* Wv = (const float*)d_in[3];
    float* out = (float*)d_out;

    cudaFuncSetAttribute(qkv_gemm,    cudaFuncAttributeMaxDynamicSharedMemorySize, SMEM3);
    cudaFuncSetAttribute(s_gemm,      cudaFuncAttributeMaxDynamicSharedMemorySize, SMEM2);
    cudaFuncSetAttribute(out_gemm_sk, cudaFuncAttributeMaxDynamicSharedMemorySize, SMEM2);

    __half *xh, *xl, *Wqh, *Wql, *Wkh, *Wkl, *Wvh, *Wvl;
    __half *qh, *kh, *kl, *vTh, *vTl, *wh;
    float* s;
    cudaGetSymbolAddress((void**)&xh,  g_xh);  cudaGetSymbolAddress((void**)&xl,  g_xl);
    cudaGetSymbolAddress((void**)&Wqh, g_Wqh); cudaGetSymbolAddress((void**)&Wql, g_Wql);
    cudaGetSymbolAddress((void**)&Wkh, g_Wkh); cudaGetSymbolAddress((void**)&Wkl, g_Wkl);
    cudaGetSymbolAddress((void**)&Wvh, g_Wvh); cudaGetSymbolAddress((void**)&Wvl, g_Wvl);
    cudaGetSymbolAddress((void**)&qh,  g_qh);
    cudaGetSymbolAddress((void**)&kh,  g_kh);  cudaGetSymbolAddress((void**)&kl,  g_kl);
    cudaGetSymbolAddress((void**)&vTh, g_vTh); cudaGetSymbolAddress((void**)&vTl, g_vTl);
    cudaGetSymbolAddress((void**)&wh,  g_wh);
    cudaGetSymbolAddress((void**)&s,   g_s);

    // 1. split inputs into fp16 hi/lo
    const int total4 = X4 + 3 * W4;
    conv_all<<<(total4 + 255) / 256, 256>>>(x, Wq, Wk, Wv,
                                            xh, xl, Wqh, Wql, Wkh, Wkl, Wvh, Wvl);

    // 2. q, k, vT in one launch (fp16x3 core)
    qkv_gemm<<<1536, 256, SMEM3>>>(xh, xl, Wqh, Wql, Wkh, Wkl, Wvh, Wvl,
                                   qh, kh, kl, vTh, vTl);

    // 3. s = q @ k^T (fp16x2 core) -> fp32
    s_gemm<<<dim3(SEQ / 128, SEQ / 128), 256, SMEM2>>>(qh, kh, kl, s);

    // 4. softmax -> w (fp16 hi only)
    softmax_rows<<<SEQ, 256>>>(s, wh);

    // 5. out = w @ vT^T, split-K (fp16x2 core) -> partials in g_s (dead)
    out_gemm_sk<<<1024, 256, SMEM2>>>(wh, vTh, vTl, s);

    // 6. final reduce
    const int n4 = SE / 4;
    reduce_add<<<(n4 + 255) / 256, 256>>>(s, out, n4);
}

// round 14
// speedup vs baseline: 2.1135x; 1.1576x over previous
#include <cuda_runtime.h>
#include <cuda_fp16.h>
#include <stdint.h>

#define SEQ 4096
#define E   2048
#define SE  (SEQ * E)
#define EE  (E * E)
#define SS  ((size_t)SEQ * SEQ)

// ---------------------------------------------------------------------------
// Scratch (__device__ globals per allocation-free rule)
// g_s: s logits (fp32) before softmax, then split-K partials for out-GEMM.
// ---------------------------------------------------------------------------
__device__ __half g_xh [SE], g_xl [SE];
__device__ __half g_Wqh[EE], g_Wql[EE];
__device__ __half g_Wkh[EE], g_Wkl[EE];
__device__ __half g_Wvh[EE];
__device__ __half g_qh [SE];                 // A-side of s-GEMM: hi only
__device__ __half g_kh [SE], g_kl [SE];
__device__ __half g_vTh[SE], g_vTl[SE];
__device__ __half g_wh [SS];                 // A-side of out-GEMM: hi only
__device__ float  g_s  [SS];

// ---------------------------------------------------------------------------
// PTX helpers
// ---------------------------------------------------------------------------
__device__ __forceinline__ uint32_t smem_u32(const void* p) {
    uint32_t a;
    asm("{ .reg .u64 t; cvta.to.shared.u64 t, %1; cvt.u32.u64 %0, t; }" : "=r"(a) : "l"(p));
    return a;
}
#define CP_ASYNC_16(dst, src) \
    asm volatile("cp.async.cg.shared.global [%0], [%1], 16;" :: "r"(dst), "l"(src))
#define CP_ASYNC_COMMIT() asm volatile("cp.async.commit_group;" ::: "memory")
#define CP_ASYNC_WAIT(n)  asm volatile("cp.async.wait_group %0;" :: "n"(n) : "memory")
#define LDSM4(r, a) \
    asm volatile("ldmatrix.sync.aligned.m8n8.x4.shared.b16 {%0,%1,%2,%3}, [%4];" \
        : "=r"((r)[0]), "=r"((r)[1]), "=r"((r)[2]), "=r"((r)[3]) : "r"(a))
#define MMAH(d, a, b0, b1) \
    asm volatile("mma.sync.aligned.m16n8k16.row.col.f32.f16.f16.f32 " \
        "{%0,%1,%2,%3}, {%4,%5,%6,%7}, {%8,%9}, {%0,%1,%2,%3};" \
        : "+f"((d)[0]), "+f"((d)[1]), "+f"((d)[2]), "+f"((d)[3]) \
        : "r"((a)[0]), "r"((a)[1]), "r"((a)[2]), "r"((a)[3]), "r"(b0), "r"(b1))
__device__ __forceinline__ uint32_t sw64(uint32_t o) { return o ^ ((o >> 3) & 0x30); }

// ===========================================================================
// CORE2 (fp16 x2): C = Ah * (Bh+Bl)^T
// 128x128 tile, BK=32, 3 tiles/stage (24KB), 5 stages (120KB), warp 64x32,
// pass-major MMA order, fragment double-buffering.
// Epilogue: fp32 Cf, or fp16 Ch (+optional Cl split).
// ===========================================================================
#define TILE_B   8192                 // 128 rows x 64B
#define ST_BH    TILE_B
#define ST_BL    (2 * TILE_B)
#define STAGE_B  (3 * TILE_B)         // 24576
#define SMEM_T   (5 * STAGE_B)        // 122880

struct Ld2 { const __half *pA, *pBh, *pBl; uint32_t d0, d1; int he; };

__device__ __forceinline__ void load_stage2(uint32_t sb, int st, const Ld2& L, int k0)
{
    uint32_t s = sb + st * STAGE_B;
    const __half* a  = L.pA  + k0 + L.he;
    const __half* b0 = L.pBh + k0 + L.he;
    const __half* b1 = L.pBl + k0 + L.he;
    CP_ASYNC_16(s + L.d0, a);            CP_ASYNC_16(s + L.d1, a + 8);
    CP_ASYNC_16(s + ST_BH + L.d0, b0);   CP_ASYNC_16(s + ST_BH + L.d1, b0 + 8);
    CP_ASYNC_16(s + ST_BL + L.d0, b1);   CP_ASYNC_16(s + ST_BL + L.d1, b1 + 8);
    CP_ASYNC_COMMIT();
}

struct Fr2 { uint32_t ah[4][4], bh[2][4], bl[2][4]; };

__device__ __forceinline__ void load_frags2(Fr2& f, uint32_t stb,
                                            uint32_t ab, uint32_t bb, int k16)
{
    #pragma unroll
    for (int mi = 0; mi < 4; ++mi) {
        const uint32_t off = ab + (uint32_t)mi * 1024 + k16 * 32;
        LDSM4(f.ah[mi], stb + sw64(off));
    }
    #pragma unroll
    for (int ng = 0; ng < 2; ++ng) {
        const uint32_t off = bb + (uint32_t)ng * 1024 + k16 * 32;
        LDSM4(f.bh[ng], stb + ST_BH + sw64(off));
        LDSM4(f.bl[ng], stb + ST_BL + sw64(off));
    }
}

__device__ __forceinline__ void mma_group2(float acc[4][4][4], const Fr2& f)
{
    #pragma unroll
    for (int mi = 0; mi < 4; ++mi)          // pass 1: Ah * Bh
        #pragma unroll
        for (int ni = 0; ni < 4; ++ni) {
            const int ng = ni >> 1, sel = (ni & 1) * 2;
            MMAH(acc[mi][ni], f.ah[mi], f.bh[ng][sel], f.bh[ng][sel + 1]);
        }
    #pragma unroll
    for (int mi = 0; mi < 4; ++mi)          // pass 2: Ah * Bl
        #pragma unroll
        for (int ni = 0; ni < 4; ++ni) {
            const int ng = ni >> 1, sel = (ni & 1) * 2;
            MMAH(acc[mi][ni], f.ah[mi], f.bl[ng][sel], f.bl[ng][sel + 1]);
        }
}

__device__ __forceinline__ void gemm_core2(
    const __half* __restrict__ A,
    const __half* __restrict__ Bh, const __half* __restrict__ Bl,
    float* __restrict__ Cf, __half* __restrict__ Ch, __half* __restrict__ Cl,
    int N, int K, int Ks, int bm, int bn)
{
    extern __shared__ __align__(1024) char smem[];
    const uint32_t sb = smem_u32(smem);
    const int tid = threadIdx.x, lane = tid & 31, wid = tid >> 5;
    const int wm = (wid & 1) * 64, wn = (wid >> 1) * 32;

    Ld2 L;
    {
        const int lrow = tid >> 1, lhalf = (tid & 1) * 32;
        uint32_t o = (uint32_t)lrow * 64 + lhalf;
        L.d0 = sw64(o); L.d1 = sw64(o + 16); L.he = lhalf >> 1;
        L.pA  = A  + (size_t)(bm + lrow) * Ks;
        L.pBh = Bh + (size_t)(bn + lrow) * Ks;
        L.pBl = Bl + (size_t)(bn + lrow) * Ks;
    }
    const uint32_t ab = (uint32_t)(wm + (lane & 15)) * 64 + (lane >> 4) * 16;
    const uint32_t bb = (uint32_t)(wn + (lane & 7) + ((lane >> 4) << 3)) * 64
                      + ((lane >> 3) & 1) * 16;

    float acc[4][4][4];
    #pragma unroll
    for (int i = 0; i < 4; ++i)
        #pragma unroll
        for (int j = 0; j < 4; ++j)
            #pragma unroll
            for (int r = 0; r < 4; ++r) acc[i][j][r] = 0.0f;

    const int nk = K / 32;
    #pragma unroll
    for (int s = 0; s < 4; ++s) load_stage2(sb, s, L, s * 32);
    CP_ASYNC_WAIT(3);
    __syncthreads();

    Fr2 fa, fb;
    load_frags2(fa, sb, ab, bb, 0);

    int st = 0, stw = 4;
    for (int i = 0; i < nk; ++i) {
        const uint32_t stb = sb + st * STAGE_B;
        load_frags2(fb, stb, ab, bb, 1);
        mma_group2(acc, fa);
        if (i + 4 < nk) load_stage2(sb, stw, L, (i + 4) * 32);
        else            CP_ASYNC_COMMIT();
        CP_ASYNC_WAIT(3);
        __syncthreads();
        if (++st  == 5) st  = 0;
        if (++stw == 5) stw = 0;
        if (i + 1 < nk) load_frags2(fa, sb + st * STAGE_B, ab, bb, 0);
        mma_group2(acc, fb);
    }

    const int er = lane >> 2, ec = (lane & 3) * 2;
    #pragma unroll
    for (int mi = 0; mi < 4; ++mi)
        #pragma unroll
        for (int ni = 0; ni < 4; ++ni) {
            const int r0 = bm + wm + mi * 16 + er;
            const int c0 = bn + wn + ni * 8 + ec;
            float* a = acc[mi][ni];
            if (Cf) {
                *(float2*)(Cf + (size_t)r0 * N + c0)       = make_float2(a[0], a[1]);
                *(float2*)(Cf + (size_t)(r0 + 8) * N + c0) = make_float2(a[2], a[3]);
            } else {
                #pragma unroll
                for (int h = 0; h < 2; ++h) {
                    float v0 = a[2 * h], v1 = a[2 * h + 1];
                    __half h0 = __float2half(v0), h1 = __float2half(v1);
                    size_t off = (size_t)(r0 + 8 * h) * N + c0;
                    *(__half2*)(Ch + off) = __halves2half2(h0, h1);
                    if (Cl) {
                        __half l0 = __float2half(v0 - __half2float(h0));
                        __half l1 = __float2half(v1 - __half2float(h1));
                        *(__half2*)(Cl + off) = __halves2half2(l0, l1);
                    }
                }
            }
        }
}

// ===========================================================================
// Driver kernels
// ===========================================================================
// Merged QKV (1536 CTAs): q = xh(Wq hi+lo) -> hi; k -> hi+lo; vT = Wvh(x hi+lo) -> hi+lo.
__global__ __launch_bounds__(256, 1)
void qkv_gemm(const __half* __restrict__ xh,  const __half* __restrict__ xl,
              const __half* __restrict__ Wqh, const __half* __restrict__ Wql,
              const __half* __restrict__ Wkh, const __half* __restrict__ Wkl,
              const __half* __restrict__ Wvh,
              __half* __restrict__ qh,
              __half* __restrict__ kh,  __half* __restrict__ kl,
              __half* __restrict__ vTh, __half* __restrict__ vTl)
{
    const int idx = blockIdx.x;
    if (idx < 1024) {
        const int j = idx & 511;
        const int bn = (j & 15) * 128, bm = (j >> 4) * 128;
        if (idx < 512)
            gemm_core2(xh, Wqh, Wql, nullptr, qh, nullptr, E, E, E, bm, bn);
        else
            gemm_core2(xh, Wkh, Wkl, nullptr, kh, kl, E, E, E, bm, bn);
    } else {
        const int j = idx - 1024;
        const int bn = (j & 31) * 128, bm = (j >> 5) * 128;
        gemm_core2(Wvh, xh, xl, nullptr, vTh, vTl, SEQ, E, E, bm, bn);
    }
}

// s = q @ k^T: A = q hi, B = k hi+lo -> fp32
__global__ __launch_bounds__(256, 1)
void s_gemm(const __half* __restrict__ qh,
            const __half* __restrict__ kh, const __half* __restrict__ kl,
            float* __restrict__ s)
{
    gemm_core2(qh, kh, kl, s, nullptr, nullptr, SEQ, E, E,
               blockIdx.y * 128, blockIdx.x * 128);
}

// out = w @ vT^T, split-K (1024 CTAs): disjoint fp32 partials
__global__ __launch_bounds__(256, 1)
void out_gemm_sk(const __half* __restrict__ wh,
                 const __half* __restrict__ vTh, const __half* __restrict__ vTl,
                 float* __restrict__ part)
{
    const int idx = blockIdx.x;
    const int h = idx >> 9;
    const int j = idx & 511;
    const int bn = (j & 15) * 128, bm = (j >> 4) * 128;
    const int koff = h * (SEQ / 2);
    gemm_core2(wh + koff, vTh + koff, vTl + koff,
               part + (size_t)h * SE, nullptr, nullptr, E, SEQ / 2, SEQ, bm, bn);
}

__global__ void reduce_add(const float* __restrict__ part, float* __restrict__ out, int n4)
{
    int i = blockIdx.x * blockDim.x + threadIdx.x;
    if (i >= n4) return;
    float4 a = ((const float4*)part)[i];
    float4 b = ((const float4*)part)[i + n4];
    ((float4*)out)[i] = make_float4(a.x + b.x, a.y + b.y, a.z + b.z, a.w + b.w);
}

// ===========================================================================
// Elementwise
// ===========================================================================
#define X4 (SE / 4)
#define W4 (EE / 4)

// x, Wq, Wk -> hi+lo; Wv -> hi only (A-side of vT GEMM)
__global__ void conv_all(const float* __restrict__ x,  const float* __restrict__ Wq,
                         const float* __restrict__ Wk, const float* __restrict__ Wv,
                         __half* __restrict__ xh,  __half* __restrict__ xl,
                         __half* __restrict__ Wqh, __half* __restrict__ Wql,
                         __half* __restrict__ Wkh, __half* __restrict__ Wkl,
                         __half* __restrict__ Wvh)
{
    int i = blockIdx.x * blockDim.x + threadIdx.x;
    const float* src; __half *hi, *lo; int off;
    if (i < X4)               { src = x;  hi = xh;  lo = xl;      off = i; }
    else if (i < X4 + W4)     { src = Wq; hi = Wqh; lo = Wql;     off = i - X4; }
    else if (i < X4 + 2 * W4) { src = Wk; hi = Wkh; lo = Wkl;     off = i - X4 - W4; }
    else if (i < X4 + 3 * W4) { src = Wv; hi = Wvh; lo = nullptr; off = i - X4 - 2 * W4; }
    else return;

    float4 v = ((const float4*)src)[off];
    __half h0 = __float2half(v.x), h1 = __float2half(v.y);
    __half h2 = __float2half(v.z), h3 = __float2half(v.w);
    ((__half2*)hi)[2 * off]     = __halves2half2(h0, h1);
    ((__half2*)hi)[2 * off + 1] = __halves2half2(h2, h3);
    if (lo) {
        __half l0 = __float2half(v.x - __half2float(h0));
        __half l1 = __float2half(v.y - __half2float(h1));
        __half l2 = __float2half(v.z - __half2float(h2));
        __half l3 = __float2half(v.w - __half2float(h3));
        ((__half2*)lo)[2 * off]     = __halves2half2(l0, l1);
        ((__half2*)lo)[2 * off + 1] = __halves2half2(l2, l3);
    }
}

// ---------------------------------------------------------------------------
// Row softmax: fp32 in (float4), fp16 hi out, scale fused
// ---------------------------------------------------------------------------
__inline__ __device__ float warp_max(float v) {
    #pragma unroll
    for (int o = 16; o > 0; o >>= 1) v = fmaxf(v, __shfl_xor_sync(0xffffffffu, v, o));
    return v;
}
__inline__ __device__ float warp_sum(float v) {
    #pragma unroll
    for (int o = 16; o > 0; o >>= 1) v += __shfl_xor_sync(0xffffffffu, v, o);
    return v;
}

__global__ __launch_bounds__(256)
void softmax_rows(const float* __restrict__ S, __half* __restrict__ Wh)
{
    const int rowi = blockIdx.x;
    const float4* p4 = (const float4*)(S + (size_t)rowi * SEQ);
    const float scale = 0.022097086912079608f;  // 1/sqrt(2048)
    const int tid = threadIdx.x, lane = tid & 31, wid = tid >> 5;

    __shared__ float red[8];

    float4 v[4];
    float m = -1e30f;
    #pragma unroll
    for (int i = 0; i < 4; ++i) {
        float4 t = p4[tid + i * 256];
        v[i] = make_float4(t.x * scale, t.y * scale, t.z * scale, t.w * scale);
        m = fmaxf(m, fmaxf(fmaxf(v[i].x, v[i].y), fmaxf(v[i].z, v[i].w)));
    }
    m = warp_max(m);
    if (lane == 0) red[wid] = m;
    __syncthreads();
    if (wid == 0) {
        float t = (lane < 8) ? red[lane] : -1e30f;
        t = warp_max(t);
        if (lane == 0) red[0] = t;
    }
    __syncthreads();
    m = red[0];
    __syncthreads();

    float sum = 0.0f;
    #pragma unroll
    for (int i = 0; i < 4; ++i) {
        v[i].x = __expf(v[i].x - m);  v[i].y = __expf(v[i].y - m);
        v[i].z = __expf(v[i].z - m);  v[i].w = __expf(v[i].w - m);
        sum += (v[i].x + v[i].y) + (v[i].z + v[i].w);
    }
    sum = warp_sum(sum);
    if (lane == 0) red[wid] = sum;
    __syncthreads();
    if (wid == 0) {
        float t = (lane < 8) ? red[lane] : 0.0f;
        t = warp_sum(t);
        if (lane == 0) red[0] = t;
    }
    __syncthreads();
    const float inv = 1.0f / red[0];

    #pragma unroll
    for (int i = 0; i < 4; ++i) {
        const size_t base = (size_t)rowi * SEQ + (size_t)(tid + i * 256) * 4;
        __half h0 = __float2half(v[i].x * inv), h1 = __float2half(v[i].y * inv);
        __half h2 = __float2half(v[i].z * inv), h3 = __float2half(v[i].w * inv);
        *(__half2*)(Wh + base)     = __halves2half2(h0, h1);
        *(__half2*)(Wh + base + 2) = __halves2half2(h2, h3);
    }
}

// ===========================================================================
// kernel_launch
// ===========================================================================
extern "C" void kernel_launch(void* const* d_in, const int* in_sizes, int n_in,
                              void* d_out, int out_size)
{
    const float* x  = (const float*)d_in[0];
    const float* Wq = (const float*)d_in[1];
    const float* Wk = (const float*)d_in[2];
    const float* Wv = (const float*)d_in[3];
    float* out = (float*)d_out;

    cudaFuncSetAttribute(qkv_gemm,    cudaFuncAttributeMaxDynamicSharedMemorySize, SMEM_T);
    cudaFuncSetAttribute(s_gemm,      cudaFuncAttributeMaxDynamicSharedMemorySize, SMEM_T);
    cudaFuncSetAttribute(out_gemm_sk, cudaFuncAttributeMaxDynamicSharedMemorySize, SMEM_T);

    __half *xh, *xl, *Wqh, *Wql, *Wkh, *Wkl, *Wvh;
    __half *qh, *kh, *kl, *vTh, *vTl, *wh;
    float* s;
    cudaGetSymbolAddress((void**)&xh,  g_xh);  cudaGetSymbolAddress((void**)&xl,  g_xl);
    cudaGetSymbolAddress((void**)&Wqh, g_Wqh); cudaGetSymbolAddress((void**)&Wql, g_Wql);
    cudaGetSymbolAddress((void**)&Wkh, g_Wkh); cudaGetSymbolAddress((void**)&Wkl, g_Wkl);
    cudaGetSymbolAddress((void**)&Wvh, g_Wvh);
    cudaGetSymbolAddress((void**)&qh,  g_qh);
    cudaGetSymbolAddress((void**)&kh,  g_kh);  cudaGetSymbolAddress((void**)&kl,  g_kl);
    cudaGetSymbolAddress((void**)&vTh, g_vTh); cudaGetSymbolAddress((void**)&vTl, g_vTl);
    cudaGetSymbolAddress((void**)&wh,  g_wh);
    cudaGetSymbolAddress((void**)&s,   g_s);

    // 1. split inputs into fp16 hi(/lo)
    const int total4 = X4 + 3 * W4;
    conv_all<<<(total4 + 255) / 256, 256>>>(x, Wq, Wk, Wv,
                                            xh, xl, Wqh, Wql, Wkh, Wkl, Wvh);

    // 2. q, k, vT in one launch (fp16x2)
    qkv_gemm<<<1536, 256, SMEM_T>>>(xh, xl, Wqh, Wql, Wkh, Wkl, Wvh,
                                    qh, kh, kl, vTh, vTl);

    // 3. s = q @ k^T (fp16x2) -> fp32
    s_gemm<<<dim3(SEQ / 128, SEQ / 128), 256, SMEM_T>>>(qh, kh, kl, s);

    // 4. softmax -> w (fp16 hi only)
    softmax_rows<<<SEQ, 256>>>(s, wh);

    // 5. out = w @ vT^T, split-K (fp16x2) -> partials in g_s (dead)
    out_gemm_sk<<<1024, 256, SMEM_T>>>(wh, vTh, vTl, s);

    // 6. final reduce
    const int n4 = SE / 4;
    reduce_add<<<(n4 + 255) / 256, 256>>>(s, out, n4);
}

// round 15
// speedup vs baseline: 2.6093x; 1.2346x over previous
#include <cuda_runtime.h>
#include <cuda_fp16.h>
#include <stdint.h>

#define SEQ 4096
#define E   2048
#define SE  (SEQ * E)
#define EE  (E * E)
#define SS  ((size_t)SEQ * SEQ)

// ---------------------------------------------------------------------------
// Scratch (__device__ globals per allocation-free rule)
// g_s: s logits (fp32) before softmax, then split-K partials for out-GEMM.
// ---------------------------------------------------------------------------
__device__ __half g_xh [SE], g_xl [SE];
__device__ __half g_Wqh[EE], g_Wql[EE];
__device__ __half g_Wkh[EE], g_Wkl[EE];
__device__ __half g_Wvh[EE];
__device__ __half g_qh [SE], g_kh [SE], g_vTh[SE];
__device__ __half g_wh [SS];
__device__ float  g_s  [SS];

// ---------------------------------------------------------------------------
// PTX helpers
// ---------------------------------------------------------------------------
__device__ __forceinline__ uint32_t smem_u32(const void* p) {
    uint32_t a;
    asm("{ .reg .u64 t; cvta.to.shared.u64 t, %1; cvt.u32.u64 %0, t; }" : "=r"(a) : "l"(p));
    return a;
}
#define CP_ASYNC_16(dst, src) \
    asm volatile("cp.async.cg.shared.global [%0], [%1], 16;" :: "r"(dst), "l"(src))
#define CP_ASYNC_COMMIT() asm volatile("cp.async.commit_group;" ::: "memory")
#define CP_ASYNC_WAIT(n)  asm volatile("cp.async.wait_group %0;" :: "n"(n) : "memory")
#define LDSM4(r, a) \
    asm volatile("ldmatrix.sync.aligned.m8n8.x4.shared.b16 {%0,%1,%2,%3}, [%4];" \
        : "=r"((r)[0]), "=r"((r)[1]), "=r"((r)[2]), "=r"((r)[3]) : "r"(a))
#define MMAH(d, a, b0, b1) \
    asm volatile("mma.sync.aligned.m16n8k16.row.col.f32.f16.f16.f32 " \
        "{%0,%1,%2,%3}, {%4,%5,%6,%7}, {%8,%9}, {%0,%1,%2,%3};" \
        : "+f"((d)[0]), "+f"((d)[1]), "+f"((d)[2]), "+f"((d)[3]) \
        : "r"((a)[0]), "r"((a)[1]), "r"((a)[2]), "r"((a)[3]), "r"(b0), "r"(b1))
__device__ __forceinline__ uint32_t sw64(uint32_t o) { return o ^ ((o >> 3) & 0x30); }

#define TILE_B   8192                 // 128 rows x 64B

// ===========================================================================
// CORE2 (fp16 x2, QKV): C = Ah * (Bh+Bl)^T -> fp16 hi
// 128x128 tile, BK=32, 3 tiles/stage (24KB), 5 stages (120KB), warp 64x32.
// ===========================================================================
#define ST_BH    TILE_B
#define ST_BL    (2 * TILE_B)
#define STAGE2   (3 * TILE_B)         // 24576
#define SMEM2    (5 * STAGE2)         // 122880

struct Ld2 { const __half *pA, *pBh, *pBl; uint32_t d0, d1; int he; };

__device__ __forceinline__ void load_stage2(uint32_t sb, int st, const Ld2& L, int k0)
{
    uint32_t s = sb + st * STAGE2;
    const __half* a  = L.pA  + k0 + L.he;
    const __half* b0 = L.pBh + k0 + L.he;
    const __half* b1 = L.pBl + k0 + L.he;
    CP_ASYNC_16(s + L.d0, a);            CP_ASYNC_16(s + L.d1, a + 8);
    CP_ASYNC_16(s + ST_BH + L.d0, b0);   CP_ASYNC_16(s + ST_BH + L.d1, b0 + 8);
    CP_ASYNC_16(s + ST_BL + L.d0, b1);   CP_ASYNC_16(s + ST_BL + L.d1, b1 + 8);
    CP_ASYNC_COMMIT();
}

struct Fr2 { uint32_t ah[4][4], bh[2][4], bl[2][4]; };

__device__ __forceinline__ void load_frags2(Fr2& f, uint32_t stb,
                                            uint32_t ab, uint32_t bb, int k16)
{
    #pragma unroll
    for (int mi = 0; mi < 4; ++mi) {
        const uint32_t off = ab + (uint32_t)mi * 1024 + k16 * 32;
        LDSM4(f.ah[mi], stb + sw64(off));
    }
    #pragma unroll
    for (int ng = 0; ng < 2; ++ng) {
        const uint32_t off = bb + (uint32_t)ng * 1024 + k16 * 32;
        LDSM4(f.bh[ng], stb + ST_BH + sw64(off));
        LDSM4(f.bl[ng], stb + ST_BL + sw64(off));
    }
}

__device__ __forceinline__ void mma_group2(float acc[4][4][4], const Fr2& f)
{
    #pragma unroll
    for (int mi = 0; mi < 4; ++mi)
        #pragma unroll
        for (int ni = 0; ni < 4; ++ni) {
            const int ng = ni >> 1, sel = (ni & 1) * 2;
            MMAH(acc[mi][ni], f.ah[mi], f.bh[ng][sel], f.bh[ng][sel + 1]);
        }
    #pragma unroll
    for (int mi = 0; mi < 4; ++mi)
        #pragma unroll
        for (int ni = 0; ni < 4; ++ni) {
            const int ng = ni >> 1, sel = (ni & 1) * 2;
            MMAH(acc[mi][ni], f.ah[mi], f.bl[ng][sel], f.bl[ng][sel + 1]);
        }
}

__device__ __forceinline__ void gemm_core2(
    const __half* __restrict__ A,
    const __half* __restrict__ Bh, const __half* __restrict__ Bl,
    __half* __restrict__ Ch, int N, int K, int bm, int bn)
{
    extern __shared__ __align__(1024) char smem[];
    const uint32_t sb = smem_u32(smem);
    const int tid = threadIdx.x, lane = tid & 31, wid = tid >> 5;
    const int wm = (wid & 1) * 64, wn = (wid >> 1) * 32;

    Ld2 L;
    {
        const int lrow = tid >> 1, lhalf = (tid & 1) * 32;
        uint32_t o = (uint32_t)lrow * 64 + lhalf;
        L.d0 = sw64(o); L.d1 = sw64(o + 16); L.he = lhalf >> 1;
        L.pA  = A  + (size_t)(bm + lrow) * K;
        L.pBh = Bh + (size_t)(bn + lrow) * K;
        L.pBl = Bl + (size_t)(bn + lrow) * K;
    }
    const uint32_t ab = (uint32_t)(wm + (lane & 15)) * 64 + (lane >> 4) * 16;
    const uint32_t bb = (uint32_t)(wn + (lane & 7) + ((lane >> 4) << 3)) * 64
                      + ((lane >> 3) & 1) * 16;

    float acc[4][4][4];
    #pragma unroll
    for (int i = 0; i < 4; ++i)
        #pragma unroll
        for (int j = 0; j < 4; ++j)
            #pragma unroll
            for (int r = 0; r < 4; ++r) acc[i][j][r] = 0.0f;

    const int nk = K / 32;
    #pragma unroll
    for (int s = 0; s < 4; ++s) load_stage2(sb, s, L, s * 32);
    CP_ASYNC_WAIT(3);
    __syncthreads();

    Fr2 fa, fb;
    load_frags2(fa, sb, ab, bb, 0);

    int st = 0, stw = 4;
    for (int i = 0; i < nk; ++i) {
        const uint32_t stb = sb + st * STAGE2;
        load_frags2(fb, stb, ab, bb, 1);
        mma_group2(acc, fa);
        if (i + 4 < nk) load_stage2(sb, stw, L, (i + 4) * 32);
        else            CP_ASYNC_COMMIT();
        CP_ASYNC_WAIT(3);
        __syncthreads();
        if (++st  == 5) st  = 0;
        if (++stw == 5) stw = 0;
        if (i + 1 < nk) load_frags2(fa, sb + st * STAGE2, ab, bb, 0);
        mma_group2(acc, fb);
    }

    const int er = lane >> 2, ec = (lane & 3) * 2;
    #pragma unroll
    for (int mi = 0; mi < 4; ++mi)
        #pragma unroll
        for (int ni = 0; ni < 4; ++ni) {
            const int r0 = bm + wm + mi * 16 + er;
            const int c0 = bn + wn + ni * 8 + ec;
            float* a = acc[mi][ni];
            #pragma unroll
            for (int h = 0; h < 2; ++h) {
                size_t off = (size_t)(r0 + 8 * h) * N + c0;
                *(__half2*)(Ch + off) =
                    __halves2half2(__float2half(a[2 * h]), __float2half(a[2 * h + 1]));
            }
        }
}

// ===========================================================================
// CORE1 (fp16 x1, s & out): C = Ah * Bh^T -> fp32
// 2 tiles/stage (16KB), 5 stages (80KB). Same pipeline protocol.
// ===========================================================================
#define STAGE1   (2 * TILE_B)         // 16384
#define SMEM1    (5 * STAGE1)         // 81920

struct Ld1 { const __half *pA, *pB; uint32_t d0, d1; int he; };

__device__ __forceinline__ void load_stage1(uint32_t sb, int st, const Ld1& L, int k0)
{
    uint32_t s = sb + st * STAGE1;
    const __half* a = L.pA + k0 + L.he;
    const __half* b = L.pB + k0 + L.he;
    CP_ASYNC_16(s + L.d0, a);            CP_ASYNC_16(s + L.d1, a + 8);
    CP_ASYNC_16(s + TILE_B + L.d0, b);   CP_ASYNC_16(s + TILE_B + L.d1, b + 8);
    CP_ASYNC_COMMIT();
}

struct Fr1 { uint32_t ah[4][4], bh[2][4]; };

__device__ __forceinline__ void load_frags1(Fr1& f, uint32_t stb,
                                            uint32_t ab, uint32_t bb, int k16)
{
    #pragma unroll
    for (int mi = 0; mi < 4; ++mi) {
        const uint32_t off = ab + (uint32_t)mi * 1024 + k16 * 32;
        LDSM4(f.ah[mi], stb + sw64(off));
    }
    #pragma unroll
    for (int ng = 0; ng < 2; ++ng) {
        const uint32_t off = bb + (uint32_t)ng * 1024 + k16 * 32;
        LDSM4(f.bh[ng], stb + TILE_B + sw64(off));
    }
}

__device__ __forceinline__ void mma_group1(float acc[4][4][4], const Fr1& f)
{
    #pragma unroll
    for (int mi = 0; mi < 4; ++mi)
        #pragma unroll
        for (int ni = 0; ni < 4; ++ni) {
            const int ng = ni >> 1, sel = (ni & 1) * 2;
            MMAH(acc[mi][ni], f.ah[mi], f.bh[ng][sel], f.bh[ng][sel + 1]);
        }
}

__device__ __forceinline__ void gemm_core1(
    const __half* __restrict__ A, const __half* __restrict__ B,
    float* __restrict__ Cf, int N, int K, int Ks, int bm, int bn)
{
    extern __shared__ __align__(1024) char smem[];
    const uint32_t sb = smem_u32(smem);
    const int tid = threadIdx.x, lane = tid & 31, wid = tid >> 5;
    const int wm = (wid & 1) * 64, wn = (wid >> 1) * 32;

    Ld1 L;
    {
        const int lrow = tid >> 1, lhalf = (tid & 1) * 32;
        uint32_t o = (uint32_t)lrow * 64 + lhalf;
        L.d0 = sw64(o); L.d1 = sw64(o + 16); L.he = lhalf >> 1;
        L.pA = A + (size_t)(bm + lrow) * Ks;
        L.pB = B + (size_t)(bn + lrow) * Ks;
    }
    const uint32_t ab = (uint32_t)(wm + (lane & 15)) * 64 + (lane >> 4) * 16;
    const uint32_t bb = (uint32_t)(wn + (lane & 7) + ((lane >> 4) << 3)) * 64
                      + ((lane >> 3) & 1) * 16;

    float acc[4][4][4];
    #pragma unroll
    for (int i = 0; i < 4; ++i)
        #pragma unroll
        for (int j = 0; j < 4; ++j)
            #pragma unroll
            for (int r = 0; r < 4; ++r) acc[i][j][r] = 0.0f;

    const int nk = K / 32;
    #pragma unroll
    for (int s = 0; s < 4; ++s) load_stage1(sb, s, L, s * 32);
    CP_ASYNC_WAIT(3);
    __syncthreads();

    Fr1 fa, fb;
    load_frags1(fa, sb, ab, bb, 0);

    int st = 0, stw = 4;
    for (int i = 0; i < nk; ++i) {
        const uint32_t stb = sb + st * STAGE1;
        load_frags1(fb, stb, ab, bb, 1);
        mma_group1(acc, fa);
        if (i + 4 < nk) load_stage1(sb, stw, L, (i + 4) * 32);
        else            CP_ASYNC_COMMIT();
        CP_ASYNC_WAIT(3);
        __syncthreads();
        if (++st  == 5) st  = 0;
        if (++stw == 5) stw = 0;
        if (i + 1 < nk) load_frags1(fa, sb + st * STAGE1, ab, bb, 0);
        mma_group1(acc, fb);
    }

    const int er = lane >> 2, ec = (lane & 3) * 2;
    #pragma unroll
    for (int mi = 0; mi < 4; ++mi)
        #pragma unroll
        for (int ni = 0; ni < 4; ++ni) {
            const int r0 = bm + wm + mi * 16 + er;
            const int c0 = bn + wn + ni * 8 + ec;
            float* a = acc[mi][ni];
            *(float2*)(Cf + (size_t)r0 * N + c0)       = make_float2(a[0], a[1]);
            *(float2*)(Cf + (size_t)(r0 + 8) * N + c0) = make_float2(a[2], a[3]);
        }
}

// ===========================================================================
// Driver kernels
// ===========================================================================
// Merged QKV (1536 CTAs, core2): all outputs hi-only.
__global__ __launch_bounds__(256, 1)
void qkv_gemm(const __half* __restrict__ xh,  const __half* __restrict__ xl,
              const __half* __restrict__ Wqh, const __half* __restrict__ Wql,
              const __half* __restrict__ Wkh, const __half* __restrict__ Wkl,
              const __half* __restrict__ Wvh,
              __half* __restrict__ qh, __half* __restrict__ kh, __half* __restrict__ vTh)
{
    const int idx = blockIdx.x;
    if (idx < 1024) {
        const int j = idx & 511;
        const int bn = (j & 15) * 128, bm = (j >> 4) * 128;
        if (idx < 512)
            gemm_core2(xh, Wqh, Wql, qh, E, E, bm, bn);
        else
            gemm_core2(xh, Wkh, Wkl, kh, E, E, bm, bn);
    } else {
        const int j = idx - 1024;
        const int bn = (j & 31) * 128, bm = (j >> 5) * 128;
        gemm_core2(Wvh, xh, xl, vTh, SEQ, E, bm, bn);
    }
}

// s = qh @ kh^T (core1) -> fp32
__global__ __launch_bounds__(256, 1)
void s_gemm(const __half* __restrict__ qh, const __half* __restrict__ kh,
            float* __restrict__ s)
{
    gemm_core1(qh, kh, s, SEQ, E, E, blockIdx.y * 128, blockIdx.x * 128);
}

// out = wh @ vTh^T, split-K (core1, 1024 CTAs): disjoint fp32 partials
__global__ __launch_bounds__(256, 1)
void out_gemm_sk(const __half* __restrict__ wh, const __half* __restrict__ vTh,
                 float* __restrict__ part)
{
    const int idx = blockIdx.x;
    const int h = idx >> 9;
    const int j = idx & 511;
    const int bn = (j & 15) * 128, bm = (j >> 4) * 128;
    const int koff = h * (SEQ / 2);
    gemm_core1(wh + koff, vTh + koff, part + (size_t)h * SE,
               E, SEQ / 2, SEQ, bm, bn);
}

__global__ void reduce_add(const float* __restrict__ part, float* __restrict__ out, int n4)
{
    int i = blockIdx.x * blockDim.x + threadIdx.x;
    if (i >= n4) return;
    float4 a = ((const float4*)part)[i];
    float4 b = ((const float4*)part)[i + n4];
    ((float4*)out)[i] = make_float4(a.x + b.x, a.y + b.y, a.z + b.z, a.w + b.w);
}

// ===========================================================================
// Elementwise
// ===========================================================================
#define X4 (SE / 4)
#define W4 (EE / 4)

// x, Wq, Wk -> hi+lo; Wv -> hi only
__global__ void conv_all(const float* __restrict__ x,  const float* __restrict__ Wq,
                         const float* __restrict__ Wk, const float* __restrict__ Wv,
                         __half* __restrict__ xh,  __half* __restrict__ xl,
                         __half* __restrict__ Wqh, __half* __restrict__ Wql,
                         __half* __restrict__ Wkh, __half* __restrict__ Wkl,
                         __half* __restrict__ Wvh)
{
    int i = blockIdx.x * blockDim.x + threadIdx.x;
    const float* src; __half *hi, *lo; int off;
    if (i < X4)               { src = x;  hi = xh;  lo = xl;      off = i; }
    else if (i < X4 + W4)     { src = Wq; hi = Wqh; lo = Wql;     off = i - X4; }
    else if (i < X4 + 2 * W4) { src = Wk; hi = Wkh; lo = Wkl;     off = i - X4 - W4; }
    else if (i < X4 + 3 * W4) { src = Wv; hi = Wvh; lo = nullptr; off = i - X4 - 2 * W4; }
    else return;

    float4 v = ((const float4*)src)[off];
    __half h0 = __float2half(v.x), h1 = __float2half(v.y);
    __half h2 = __float2half(v.z), h3 = __float2half(v.w);
    ((__half2*)hi)[2 * off]     = __halves2half2(h0, h1);
    ((__half2*)hi)[2 * off + 1] = __halves2half2(h2, h3);
    if (lo) {
        __half l0 = __float2half(v.x - __half2float(h0));
        __half l1 = __float2half(v.y - __half2float(h1));
        __half l2 = __float2half(v.z - __half2float(h2));
        __half l3 = __float2half(v.w - __half2float(h3));
        ((__half2*)lo)[2 * off]     = __halves2half2(l0, l1);
        ((__half2*)lo)[2 * off + 1] = __halves2half2(l2, l3);
    }
}

// ---------------------------------------------------------------------------
// Row softmax: fp32 in (float4), fp16 hi out, scale fused
// ---------------------------------------------------------------------------
__inline__ __device__ float warp_max(float v) {
    #pragma unroll
    for (int o = 16; o > 0; o >>= 1) v = fmaxf(v, __shfl_xor_sync(0xffffffffu, v, o));
    return v;
}
__inline__ __device__ float warp_sum(float v) {
    #pragma unroll
    for (int o = 16; o > 0; o >>= 1) v += __shfl_xor_sync(0xffffffffu, v, o);
    return v;
}

__global__ __launch_bounds__(256)
void softmax_rows(const float* __restrict__ S, __half* __restrict__ Wh)
{
    const int rowi = blockIdx.x;
    const float4* p4 = (const float4*)(S + (size_t)rowi * SEQ);
    const float scale = 0.022097086912079608f;  // 1/sqrt(2048)
    const int tid = threadIdx.x, lane = tid & 31, wid = tid >> 5;

    __shared__ float red[8];

    float4 v[4];
    float m = -1e30f;
    #pragma unroll
    for (int i = 0; i < 4; ++i) {
        float4 t = p4[tid + i * 256];
        v[i] = make_float4(t.x * scale, t.y * scale, t.z * scale, t.w * scale);
        m = fmaxf(m, fmaxf(fmaxf(v[i].x, v[i].y), fmaxf(v[i].z, v[i].w)));
    }
    m = warp_max(m);
    if (lane == 0) red[wid] = m;
    __syncthreads();
    if (wid == 0) {
        float t = (lane < 8) ? red[lane] : -1e30f;
        t = warp_max(t);
        if (lane == 0) red[0] = t;
    }
    __syncthreads();
    m = red[0];
    __syncthreads();

    float sum = 0.0f;
    #pragma unroll
    for (int i = 0; i < 4; ++i) {
        v[i].x = __expf(v[i].x - m);  v[i].y = __expf(v[i].y - m);
        v[i].z = __expf(v[i].z - m);  v[i].w = __expf(v[i].w - m);
        sum += (v[i].x + v[i].y) + (v[i].z + v[i].w);
    }
    sum = warp_sum(sum);
    if (lane == 0) red[wid] = sum;
    __syncthreads();
    if (wid == 0) {
        float t = (lane < 8) ? red[lane] : 0.0f;
        t = warp_sum(t);
        if (lane == 0) red[0] = t;
    }
    __syncthreads();
    const float inv = 1.0f / red[0];

    #pragma unroll
    for (int i = 0; i < 4; ++i) {
        const size_t base = (size_t)rowi * SEQ + (size_t)(tid + i * 256) * 4;
        __half h0 = __float2half(v[i].x * inv), h1 = __float2half(v[i].y * inv);
        __half h2 = __float2half(v[i].z * inv), h3 = __float2half(v[i].w * inv);
        *(__half2*)(Wh + base)     = __halves2half2(h0, h1);
        *(__half2*)(Wh + base + 2) = __halves2half2(h2, h3);
    }
}

// ===========================================================================
// kernel_launch
// ===========================================================================
extern "C" void kernel_launch(void* const* d_in, const int* in_sizes, int n_in,
                              void* d_out, int out_size)
{
    const float* x  = (const float*)d_in[0];
    const float* Wq = (const float*)d_in[1];
    const float* Wk = (const float*)d_in[2];
    const float* Wv = (const float*)d_in[3];
    float* out = (float*)d_out;

    cudaFuncSetAttribute(qkv_gemm,    cudaFuncAttributeMaxDynamicSharedMemorySize, SMEM2);
    cudaFuncSetAttribute(s_gemm,      cudaFuncAttributeMaxDynamicSharedMemorySize, SMEM1);
    cudaFuncSetAttribute(out_gemm_sk, cudaFuncAttributeMaxDynamicSharedMemorySize, SMEM1);

    __half *xh, *xl, *Wqh, *Wql, *Wkh, *Wkl, *Wvh;
    __half *qh, *kh, *vTh, *wh;
    float* s;
    cudaGetSymbolAddress((void**)&xh,  g_xh);  cudaGetSymbolAddress((void**)&xl,  g_xl);
    cudaGetSymbolAddress((void**)&Wqh, g_Wqh); cudaGetSymbolAddress((void**)&Wql, g_Wql);
    cudaGetSymbolAddress((void**)&Wkh, g_Wkh); cudaGetSymbolAddress((void**)&Wkl, g_Wkl);
    cudaGetSymbolAddress((void**)&Wvh, g_Wvh);
    cudaGetSymbolAddress((void**)&qh,  g_qh);
    cudaGetSymbolAddress((void**)&kh,  g_kh);
    cudaGetSymbolAddress((void**)&vTh, g_vTh);
    cudaGetSymbolAddress((void**)&wh,  g_wh);
    cudaGetSymbolAddress((void**)&s,   g_s);

    // 1. split inputs into fp16 hi(/lo)
    const int total4 = X4 + 3 * W4;
    conv_all<<<(total4 + 255) / 256, 256>>>(x, Wq, Wk, Wv,
                                            xh, xl, Wqh, Wql, Wkh, Wkl, Wvh);

    // 2. q, k, vT in one launch (2-pass core)
    qkv_gemm<<<1536, 256, SMEM2>>>(xh, xl, Wqh, Wql, Wkh, Wkl, Wvh, qh, kh, vTh);

    // 3. s = q @ k^T (1-pass core) -> fp32
    s_gemm<<<dim3(SEQ / 128, SEQ / 128), 256, SMEM1>>>(qh, kh, s);

    // 4. softmax -> w (fp16 hi)
    softmax_rows<<<SEQ, 256>>>(s, wh);

    // 5. out = w @ vT^T, split-K (1-pass core) -> partials in g_s (dead)
    out_gemm_sk<<<1024, 256, SMEM1>>>(wh, vTh, s);

    // 6. final reduce
    const int n4 = SE / 4;
    reduce_add<<<(n4 + 255) / 256, 256>>>(s, out, n4);
}

// round 16
// speedup vs baseline: 3.1711x; 1.2153x over previous
#include <cuda_runtime.h>
#include <cuda_fp16.h>
#include <stdint.h>

#define SEQ 4096
#define E   2048
#define SE  (SEQ * E)
#define EE  (E * E)
#define SS  ((size_t)SEQ * SEQ)

// ---------------------------------------------------------------------------
// Scratch (__device__ globals per allocation-free rule)
// g_s: s logits (fp32) before softmax, then split-K partials for out-GEMM.
// ---------------------------------------------------------------------------
__device__ __half g_xh [SE];
__device__ __half g_Wqh[EE], g_Wkh[EE], g_Wvh[EE];
__device__ __half g_qh [SE], g_kh [SE], g_vTh[SE];
__device__ __half g_wh [SS];
__device__ float  g_s  [SS];

// ---------------------------------------------------------------------------
// PTX helpers
// ---------------------------------------------------------------------------
__device__ __forceinline__ uint32_t smem_u32(const void* p) {
    uint32_t a;
    asm("{ .reg .u64 t; cvta.to.shared.u64 t, %1; cvt.u32.u64 %0, t; }" : "=r"(a) : "l"(p));
    return a;
}
#define CP_ASYNC_16(dst, src) \
    asm volatile("cp.async.cg.shared.global [%0], [%1], 16;" :: "r"(dst), "l"(src))
#define CP_ASYNC_COMMIT() asm volatile("cp.async.commit_group;" ::: "memory")
#define CP_ASYNC_WAIT(n)  asm volatile("cp.async.wait_group %0;" :: "n"(n) : "memory")
#define LDSM4(r, a) \
    asm volatile("ldmatrix.sync.aligned.m8n8.x4.shared.b16 {%0,%1,%2,%3}, [%4];" \
        : "=r"((r)[0]), "=r"((r)[1]), "=r"((r)[2]), "=r"((r)[3]) : "r"(a))
#define MMAH(d, a, b0, b1) \
    asm volatile("mma.sync.aligned.m16n8k16.row.col.f32.f16.f16.f32 " \
        "{%0,%1,%2,%3}, {%4,%5,%6,%7}, {%8,%9}, {%0,%1,%2,%3};" \
        : "+f"((d)[0]), "+f"((d)[1]), "+f"((d)[2]), "+f"((d)[3]) \
        : "r"((a)[0]), "r"((a)[1]), "r"((a)[2]), "r"((a)[3]), "r"(b0), "r"(b1))
__device__ __forceinline__ uint32_t sw64(uint32_t o) { return o ^ ((o >> 3) & 0x30); }

#define TILE_B   8192                 // 128 rows x 64B

// ===========================================================================
// CORE1 (fp16, 1-pass): C = A * B^T
// 128x128 tile, BK=32, 2 tiles/stage (16KB), 5 stages (80KB), warp 64x32,
// fragment double-buffering, proven pipeline protocol.
// Epilogue: fp32 Cf if non-null, else fp16 Ch.
// ===========================================================================
#define STAGE1   (2 * TILE_B)         // 16384
#define SMEM1    (5 * STAGE1)         // 81920

struct Ld1 { const __half *pA, *pB; uint32_t d0, d1; int he; };

__device__ __forceinline__ void load_stage1(uint32_t sb, int st, const Ld1& L, int k0)
{
    uint32_t s = sb + st * STAGE1;
    const __half* a = L.pA + k0 + L.he;
    const __half* b = L.pB + k0 + L.he;
    CP_ASYNC_16(s + L.d0, a);            CP_ASYNC_16(s + L.d1, a + 8);
    CP_ASYNC_16(s + TILE_B + L.d0, b);   CP_ASYNC_16(s + TILE_B + L.d1, b + 8);
    CP_ASYNC_COMMIT();
}

struct Fr1 { uint32_t ah[4][4], bh[2][4]; };

__device__ __forceinline__ void load_frags1(Fr1& f, uint32_t stb,
                                            uint32_t ab, uint32_t bb, int k16)
{
    #pragma unroll
    for (int mi = 0; mi < 4; ++mi) {
        const uint32_t off = ab + (uint32_t)mi * 1024 + k16 * 32;
        LDSM4(f.ah[mi], stb + sw64(off));
    }
    #pragma unroll
    for (int ng = 0; ng < 2; ++ng) {
        const uint32_t off = bb + (uint32_t)ng * 1024 + k16 * 32;
        LDSM4(f.bh[ng], stb + TILE_B + sw64(off));
    }
}

__device__ __forceinline__ void mma_group1(float acc[4][4][4], const Fr1& f)
{
    #pragma unroll
    for (int mi = 0; mi < 4; ++mi)
        #pragma unroll
        for (int ni = 0; ni < 4; ++ni) {
            const int ng = ni >> 1, sel = (ni & 1) * 2;
            MMAH(acc[mi][ni], f.ah[mi], f.bh[ng][sel], f.bh[ng][sel + 1]);
        }
}

__device__ __forceinline__ void gemm_core1(
    const __half* __restrict__ A, const __half* __restrict__ B,
    float* __restrict__ Cf, __half* __restrict__ Ch,
    int N, int K, int Ks, int bm, int bn)
{
    extern __shared__ __align__(1024) char smem[];
    const uint32_t sb = smem_u32(smem);
    const int tid = threadIdx.x, lane = tid & 31, wid = tid >> 5;
    const int wm = (wid & 1) * 64, wn = (wid >> 1) * 32;

    Ld1 L;
    {
        const int lrow = tid >> 1, lhalf = (tid & 1) * 32;
        uint32_t o = (uint32_t)lrow * 64 + lhalf;
        L.d0 = sw64(o); L.d1 = sw64(o + 16); L.he = lhalf >> 1;
        L.pA = A + (size_t)(bm + lrow) * Ks;
        L.pB = B + (size_t)(bn + lrow) * Ks;
    }
    const uint32_t ab = (uint32_t)(wm + (lane & 15)) * 64 + (lane >> 4) * 16;
    const uint32_t bb = (uint32_t)(wn + (lane & 7) + ((lane >> 4) << 3)) * 64
                      + ((lane >> 3) & 1) * 16;

    float acc[4][4][4];
    #pragma unroll
    for (int i = 0; i < 4; ++i)
        #pragma unroll
        for (int j = 0; j < 4; ++j)
            #pragma unroll
            for (int r = 0; r < 4; ++r) acc[i][j][r] = 0.0f;

    const int nk = K / 32;
    #pragma unroll
    for (int s = 0; s < 4; ++s) load_stage1(sb, s, L, s * 32);
    CP_ASYNC_WAIT(3);
    __syncthreads();

    Fr1 fa, fb;
    load_frags1(fa, sb, ab, bb, 0);

    int st = 0, stw = 4;
    for (int i = 0; i < nk; ++i) {
        const uint32_t stb = sb + st * STAGE1;
        load_frags1(fb, stb, ab, bb, 1);
        mma_group1(acc, fa);
        if (i + 4 < nk) load_stage1(sb, stw, L, (i + 4) * 32);
        else            CP_ASYNC_COMMIT();
        CP_ASYNC_WAIT(3);
        __syncthreads();
        if (++st  == 5) st  = 0;
        if (++stw == 5) stw = 0;
        if (i + 1 < nk) load_frags1(fa, sb + st * STAGE1, ab, bb, 0);
        mma_group1(acc, fb);
    }

    const int er = lane >> 2, ec = (lane & 3) * 2;
    #pragma unroll
    for (int mi = 0; mi < 4; ++mi)
        #pragma unroll
        for (int ni = 0; ni < 4; ++ni) {
            const int r0 = bm + wm + mi * 16 + er;
            const int c0 = bn + wn + ni * 8 + ec;
            float* a = acc[mi][ni];
            if (Cf) {
                *(float2*)(Cf + (size_t)r0 * N + c0)       = make_float2(a[0], a[1]);
                *(float2*)(Cf + (size_t)(r0 + 8) * N + c0) = make_float2(a[2], a[3]);
            } else {
                #pragma unroll
                for (int h = 0; h < 2; ++h) {
                    size_t off = (size_t)(r0 + 8 * h) * N + c0;
                    *(__half2*)(Ch + off) =
                        __halves2half2(__float2half(a[2 * h]), __float2half(a[2 * h + 1]));
                }
            }
        }
}

// ===========================================================================
// Driver kernels
// ===========================================================================
// Merged QKV (1536 CTAs): q = xh Wqh^T, k = xh Wkh^T, vT = Wvh xh^T (all 1-pass)
__global__ __launch_bounds__(256, 1)
void qkv_gemm(const __half* __restrict__ xh,
              const __half* __restrict__ Wqh, const __half* __restrict__ Wkh,
              const __half* __restrict__ Wvh,
              __half* __restrict__ qh, __half* __restrict__ kh, __half* __restrict__ vTh)
{
    const int idx = blockIdx.x;
    if (idx < 1024) {
        const int j = idx & 511;
        const int bn = (j & 15) * 128, bm = (j >> 4) * 128;
        if (idx < 512)
            gemm_core1(xh, Wqh, nullptr, qh, E, E, E, bm, bn);
        else
            gemm_core1(xh, Wkh, nullptr, kh, E, E, E, bm, bn);
    } else {
        const int j = idx - 1024;
        const int bn = (j & 31) * 128, bm = (j >> 5) * 128;
        gemm_core1(Wvh, xh, nullptr, vTh, SEQ, E, E, bm, bn);
    }
}

// s = qh @ kh^T -> fp32
__global__ __launch_bounds__(256, 1)
void s_gemm(const __half* __restrict__ qh, const __half* __restrict__ kh,
            float* __restrict__ s)
{
    gemm_core1(qh, kh, s, nullptr, SEQ, E, E, blockIdx.y * 128, blockIdx.x * 128);
}

// out = wh @ vTh^T, split-K (1024 CTAs): disjoint fp32 partials
__global__ __launch_bounds__(256, 1)
void out_gemm_sk(const __half* __restrict__ wh, const __half* __restrict__ vTh,
                 float* __restrict__ part)
{
    const int idx = blockIdx.x;
    const int h = idx >> 9;
    const int j = idx & 511;
    const int bn = (j & 15) * 128, bm = (j >> 4) * 128;
    const int koff = h * (SEQ / 2);
    gemm_core1(wh + koff, vTh + koff, part + (size_t)h * SE, nullptr,
               E, SEQ / 2, SEQ, bm, bn);
}

__global__ void reduce_add(const float* __restrict__ part, float* __restrict__ out, int n4)
{
    int i = blockIdx.x * blockDim.x + threadIdx.x;
    if (i >= n4) return;
    float4 a = ((const float4*)part)[i];
    float4 b = ((const float4*)part)[i + n4];
    ((float4*)out)[i] = make_float4(a.x + b.x, a.y + b.y, a.z + b.z, a.w + b.w);
}

// ===========================================================================
// Elementwise
// ===========================================================================
#define X4 (SE / 4)
#define W4 (EE / 4)

// fp32 -> fp16 (hi only), all four inputs in one launch
__global__ void conv_all(const float* __restrict__ x,  const float* __restrict__ Wq,
                         const float* __restrict__ Wk, const float* __restrict__ Wv,
                         __half* __restrict__ xh, __half* __restrict__ Wqh,
                         __half* __restrict__ Wkh, __half* __restrict__ Wvh)
{
    int i = blockIdx.x * blockDim.x + threadIdx.x;
    const float* src; __half* hi; int off;
    if (i < X4)               { src = x;  hi = xh;  off = i; }
    else if (i < X4 + W4)     { src = Wq; hi = Wqh; off = i - X4; }
    else if (i < X4 + 2 * W4) { src = Wk; hi = Wkh; off = i - X4 - W4; }
    else if (i < X4 + 3 * W4) { src = Wv; hi = Wvh; off = i - X4 - 2 * W4; }
    else return;

    float4 v = ((const float4*)src)[off];
    ((__half2*)hi)[2 * off]     = __halves2half2(__float2half(v.x), __float2half(v.y));
    ((__half2*)hi)[2 * off + 1] = __halves2half2(__float2half(v.z), __float2half(v.w));
}

// ---------------------------------------------------------------------------
// Row softmax: fp32 in (float4), fp16 hi out, scale fused
// ---------------------------------------------------------------------------
__inline__ __device__ float warp_max(float v) {
    #pragma unroll
    for (int o = 16; o > 0; o >>= 1) v = fmaxf(v, __shfl_xor_sync(0xffffffffu, v, o));
    return v;
}
__inline__ __device__ float warp_sum(float v) {
    #pragma unroll
    for (int o = 16; o > 0; o >>= 1) v += __shfl_xor_sync(0xffffffffu, v, o);
    return v;
}

__global__ __launch_bounds__(256)
void softmax_rows(const float* __restrict__ S, __half* __restrict__ Wh)
{
    const int rowi = blockIdx.x;
    const float4* p4 = (const float4*)(S + (size_t)rowi * SEQ);
    const float scale = 0.022097086912079608f;  // 1/sqrt(2048)
    const int tid = threadIdx.x, lane = tid & 31, wid = tid >> 5;

    __shared__ float red[8];

    float4 v[4];
    float m = -1e30f;
    #pragma unroll
    for (int i = 0; i < 4; ++i) {
        float4 t = p4[tid + i * 256];
        v[i] = make_float4(t.x * scale, t.y * scale, t.z * scale, t.w * scale);
        m = fmaxf(m, fmaxf(fmaxf(v[i].x, v[i].y), fmaxf(v[i].z, v[i].w)));
    }
    m = warp_max(m);
    if (lane == 0) red[wid] = m;
    __syncthreads();
    if (wid == 0) {
        float t = (lane < 8) ? red[lane] : -1e30f;
        t = warp_max(t);
        if (lane == 0) red[0] = t;
    }
    __syncthreads();
    m = red[0];
    __syncthreads();

    float sum = 0.0f;
    #pragma unroll
    for (int i = 0; i < 4; ++i) {
        v[i].x = __expf(v[i].x - m);  v[i].y = __expf(v[i].y - m);
        v[i].z = __expf(v[i].z - m);  v[i].w = __expf(v[i].w - m);
        sum += (v[i].x + v[i].y) + (v[i].z + v[i].w);
    }
    sum = warp_sum(sum);
    if (lane == 0) red[wid] = sum;
    __syncthreads();
    if (wid == 0) {
        float t = (lane < 8) ? red[lane] : 0.0f;
        t = warp_sum(t);
        if (lane == 0) red[0] = t;
    }
    __syncthreads();
    const float inv = 1.0f / red[0];

    #pragma unroll
    for (int i = 0; i < 4; ++i) {
        const size_t base = (size_t)rowi * SEQ + (size_t)(tid + i * 256) * 4;
        __half h0 = __float2half(v[i].x * inv), h1 = __float2half(v[i].y * inv);
        __half h2 = __float2half(v[i].z * inv), h3 = __float2half(v[i].w * inv);
        *(__half2*)(Wh + base)     = __halves2half2(h0, h1);
        *(__half2*)(Wh + base + 2) = __halves2half2(h2, h3);
    }
}

// ===========================================================================
// kernel_launch
// ===========================================================================
extern "C" void kernel_launch(void* const* d_in, const int* in_sizes, int n_in,
                              void* d_out, int out_size)
{
    const float* x  = (const float*)d_in[0];
    const float* Wq = (const float*)d_in[1];
    const float* Wk = (const float*)d_in[2];
    const float* Wv = (const float*)d_in[3];
    float* out = (float*)d_out;

    cudaFuncSetAttribute(qkv_gemm,    cudaFuncAttributeMaxDynamicSharedMemorySize, SMEM1);
    cudaFuncSetAttribute(s_gemm,      cudaFuncAttributeMaxDynamicSharedMemorySize, SMEM1);
    cudaFuncSetAttribute(out_gemm_sk, cudaFuncAttributeMaxDynamicSharedMemorySize, SMEM1);

    __half *xh, *Wqh, *Wkh, *Wvh, *qh, *kh, *vTh, *wh;
    float* s;
    cudaGetSymbolAddress((void**)&xh,  g_xh);
    cudaGetSymbolAddress((void**)&Wqh, g_Wqh);
    cudaGetSymbolAddress((void**)&Wkh, g_Wkh);
    cudaGetSymbolAddress((void**)&Wvh, g_Wvh);
    cudaGetSymbolAddress((void**)&qh,  g_qh);
    cudaGetSymbolAddress((void**)&kh,  g_kh);
    cudaGetSymbolAddress((void**)&vTh, g_vTh);
    cudaGetSymbolAddress((void**)&wh,  g_wh);
    cudaGetSymbolAddress((void**)&s,   g_s);

    // 1. convert inputs to fp16
    const int total4 = X4 + 3 * W4;
    conv_all<<<(total4 + 255) / 256, 256>>>(x, Wq, Wk, Wv, xh, Wqh, Wkh, Wvh);

    // 2. q, k, vT in one launch (1-pass)
    qkv_gemm<<<1536, 256, SMEM1>>>(xh, Wqh, Wkh, Wvh, qh, kh, vTh);

    // 3. s = q @ k^T -> fp32
    s_gemm<<<dim3(SEQ / 128, SEQ / 128), 256, SMEM1>>>(qh, kh, s);

    // 4. softmax -> w (fp16)
    softmax_rows<<<SEQ, 256>>>(s, wh);

    // 5. out = w @ vT^T, split-K -> partials in g_s (dead after softmax)
    out_gemm_sk<<<1024, 256, SMEM1>>>(wh, vTh, s);

    // 6. final reduce
    const int n4 = SE / 4;
    reduce_add<<<(n4 + 255) / 256, 256>>>(s, out, n4);
}